// round 6
// baseline (speedup 1.0000x reference)
#include <cuda_runtime.h>
#include <cstdint>

#define Nn 50000
#define Ee 800000
#define Gg 512
#define NBLK 196   // ceil(Nn/256)

// ---------------- scratch ----------------------------------------------------
__device__ __align__(16) float  g_P[(size_t)Nn * 256];    // [N][256]: 0..127 src_p, 128..255 dst_p
__device__ __align__(16) float  g_logits[(size_t)Ee * 8];
__device__ __align__(16) float2 g_md[(size_t)Nn * 8];     // per (node,head): (local max, local denom)
__device__ __align__(16) int    g_deg[Nn];                // zero-init; self-cleaned each pass
__device__ __align__(16) int    g_off[Nn + 1];
__device__ __align__(16) int    g_cur[Nn];
__device__ __align__(16) int    g_srcidx[Ee];
__device__ __align__(16) int    g_part[256];
__device__ unsigned g_maxenc;   // zero-init; reset in k_scanB each pass

// ---------------- f32x2 packed helpers ---------------------------------------
typedef unsigned long long u64;
__device__ __forceinline__ u64 p2(float lo, float hi) {
    u64 r;
    asm("mov.b64 %0, {%1, %2};" : "=l"(r) : "r"(__float_as_uint(lo)), "r"(__float_as_uint(hi)));
    return r;
}
__device__ __forceinline__ void fma2(u64& d, u64 a, u64 b) {
    asm("fma.rn.f32x2 %0, %1, %2, %3;" : "=l"(d) : "l"(a), "l"(b), "l"(d));
}
__device__ __forceinline__ float2 up2(u64 v) {
    unsigned lo, hi;
    asm("mov.b64 {%0, %1}, %2;" : "=r"(lo), "=r"(hi) : "l"(v));
    return make_float2(__uint_as_float(lo), __uint_as_float(hi));
}

__device__ __forceinline__ unsigned encf(float f) {
    unsigned u = __float_as_uint(f);
    return (u & 0x80000000u) ? ~u : (u | 0x80000000u);
}
__device__ __forceinline__ float decf(unsigned e) {
    unsigned u = (e & 0x80000000u) ? (e & 0x7fffffffu) : ~e;
    return __uint_as_float(u);
}

// ---------------- K: degree histogram (g_deg pre-zeroed) ---------------------
__global__ void k_deg(const int* __restrict__ ei) {
    int e = blockIdx.x * blockDim.x + threadIdx.x;
    if (e < Ee) atomicAdd(&g_deg[ei[Ee + e]], 1);
}

// ---------------- scan A/B/C -------------------------------------------------
__global__ void k_scanA() {
    int b = blockIdx.x, t = threadIdx.x;
    int i = b * 256 + t;
    int v = (i < Nn) ? g_deg[i] : 0;
#pragma unroll
    for (int o = 16; o; o >>= 1) v += __shfl_xor_sync(0xffffffffu, v, o);
    __shared__ int sm[8];
    if ((t & 31) == 0) sm[t >> 5] = v;
    __syncthreads();
    if (t == 0) {
        int s = 0;
#pragma unroll
        for (int w = 0; w < 8; w++) s += sm[w];
        g_part[b] = s;
    }
}
__global__ void k_scanB() {
    int t = threadIdx.x;          // 256
    if (t == 0) g_maxenc = 0u;    // reset for this pass (used later by k_logits)
    int v = (t < NBLK) ? g_part[t] : 0;
    int orig = v;
    int lane = t & 31, w = t >> 5;
#pragma unroll
    for (int o = 1; o < 32; o <<= 1) {
        int u = __shfl_up_sync(0xffffffffu, v, o);
        if (lane >= o) v += u;
    }
    __shared__ int wsum[8];
    if (lane == 31) wsum[w] = v;
    __syncthreads();
    if (w == 0) {
        int z = (lane < 8) ? wsum[lane] : 0;
#pragma unroll
        for (int o = 1; o < 8; o <<= 1) {
            int u = __shfl_up_sync(0xffffffffu, z, o);
            if (lane >= o) z += u;
        }
        if (lane < 8) wsum[lane] = z;
    }
    __syncthreads();
    int incl = v + (w ? wsum[w - 1] : 0);
    g_part[t] = incl - orig;
    if (t == 255) g_off[Nn] = incl;
}
__global__ void k_scanC() {
    int b = blockIdx.x, t = threadIdx.x;
    int i = b * 256 + t;
    int v = (i < Nn) ? g_deg[i] : 0;
    if (i < Nn) g_deg[i] = 0;     // self-clean for next pass
    int orig = v;
    int lane = t & 31, w = t >> 5;
#pragma unroll
    for (int o = 1; o < 32; o <<= 1) {
        int u = __shfl_up_sync(0xffffffffu, v, o);
        if (lane >= o) v += u;
    }
    __shared__ int wsum[8];
    if (lane == 31) wsum[w] = v;
    __syncthreads();
    if (w == 0) {
        int z = (lane < 8) ? wsum[lane] : 0;
#pragma unroll
        for (int o = 1; o < 8; o <<= 1) {
            int u = __shfl_up_sync(0xffffffffu, z, o);
            if (lane >= o) z += u;
        }
        if (lane < 8) wsum[lane] = z;
    }
    __syncthreads();
    int excl = v - orig + (w ? wsum[w - 1] : 0) + g_part[b];
    if (i < Nn) { g_off[i] = excl; g_cur[i] = excl; }
}

// ---------------- K1: P = x @ W^T, 64x64 tile, packed FFMA2 ------------------
__global__ void k_proj(const float* __restrict__ x,
                       const float* __restrict__ Wsrc,
                       const float* __restrict__ Wdst) {
    __shared__ __align__(16) float xs[16 * 64];   // [k][row]
    __shared__ __align__(16) float ws[16 * 64];   // [k][col]
    int m  = blockIdx.y >> 1;
    int ch = blockIdx.y & 1;
    const float* W = m ? Wdst : Wsrc;
    int t  = threadIdx.x;
    int tr = t >> 4, tc = t & 15;
    int rb = blockIdx.x * 64;
    u64 acc[4][2];
#pragma unroll
    for (int i = 0; i < 4; i++) { acc[i][0] = 0ull; acc[i][1] = 0ull; }

    for (int kc = 0; kc < 128; kc += 16) {
        __syncthreads();
#pragma unroll
        for (int u = 0; u < 4; u++) {
            int idx = t + u * 256;
            int r = idx & 63, kk = idx >> 6;
            int row = rb + r;
            xs[kk * 64 + r] = (row < Nn) ? x[(size_t)row * 128 + kc + kk] : 0.f;
            ws[kk * 64 + r] = W[(size_t)(ch * 64 + r) * 128 + kc + kk];
        }
        __syncthreads();
#pragma unroll
        for (int kk = 0; kk < 16; kk++) {
            float4 xv = *(const float4*)&xs[kk * 64 + tr * 4];
            ulonglong2 wv = *(const ulonglong2*)&ws[kk * 64 + tc * 4];
            u64 xd0 = p2(xv.x, xv.x), xd1 = p2(xv.y, xv.y);
            u64 xd2 = p2(xv.z, xv.z), xd3 = p2(xv.w, xv.w);
            fma2(acc[0][0], xd0, wv.x); fma2(acc[0][1], xd0, wv.y);
            fma2(acc[1][0], xd1, wv.x); fma2(acc[1][1], xd1, wv.y);
            fma2(acc[2][0], xd2, wv.x); fma2(acc[2][1], xd2, wv.y);
            fma2(acc[3][0], xd3, wv.x); fma2(acc[3][1], xd3, wv.y);
        }
    }
#pragma unroll
    for (int i = 0; i < 4; i++) {
        int row = rb + tr * 4 + i;
        if (row < Nn) {
            ulonglong2 v; v.x = acc[i][0]; v.y = acc[i][1];
            *(ulonglong2*)&g_P[(size_t)row * 256 + m * 128 + ch * 64 + tc * 4] = v;
        }
    }
}

// ---------------- K4: scatter edges into CSR slots ---------------------------
__global__ void k_scatter(const int* __restrict__ ei) {
    int e = blockIdx.x * blockDim.x + threadIdx.x;
    if (e < Ee) {
        int d = ei[Ee + e];
        int pos = atomicAdd(&g_cur[d], 1);
        g_srcidx[pos] = ei[e];
    }
}

// ---------------- K5: logits + per-(node,head) online softmax state ----------
// one warp per dst node; lane l owns channels [4l,4l+4); head h = l>>2
__global__ void k_logits(const float* __restrict__ attn) {
    int wid = (blockIdx.x * blockDim.x + threadIdx.x) >> 5;
    int l = threadIdx.x & 31;
    if (wid >= Nn) return;
    int n = wid;
    const float4 dp = *(const float4*)&g_P[(size_t)n * 256 + 128 + 4 * l];
    float a0 = attn[4 * l], a1 = attn[4 * l + 1], a2 = attn[4 * l + 2], a3 = attn[4 * l + 3];
    float a0q = 0.2f * a0, a1q = 0.2f * a1, a2q = 0.2f * a2, a3q = 0.2f * a3;
    int beg = g_off[n], end = g_off[n + 1];
    float mh = -3.402823466e38f;   // per-head running max (quad-duplicated)
    float dh = 0.f;                // per-head running denom
    int i = beg;
    for (; i + 3 < end; i += 4) {
        int s0 = g_srcidx[i],     s1 = g_srcidx[i + 1];
        int s2 = g_srcidx[i + 2], s3 = g_srcidx[i + 3];
        float4 q[4];
        q[0] = *(const float4*)&g_P[(size_t)s0 * 256 + 4 * l];
        q[1] = *(const float4*)&g_P[(size_t)s1 * 256 + 4 * l];
        q[2] = *(const float4*)&g_P[(size_t)s2 * 256 + 4 * l];
        q[3] = *(const float4*)&g_P[(size_t)s3 * 256 + 4 * l];
        float p[4];
#pragma unroll
        for (int j = 0; j < 4; j++) {
            float ex = q[j].x + dp.x, ey = q[j].y + dp.y;
            float ez = q[j].z + dp.z, ew = q[j].w + dp.w;
            p[j] = a0 * fmaxf(ex, 0.f) + a0q * fminf(ex, 0.f)
                 + a1 * fmaxf(ey, 0.f) + a1q * fminf(ey, 0.f)
                 + a2 * fmaxf(ez, 0.f) + a2q * fminf(ez, 0.f)
                 + a3 * fmaxf(ew, 0.f) + a3q * fminf(ew, 0.f);
        }
#pragma unroll
        for (int j = 0; j < 4; j++) p[j] += __shfl_xor_sync(0xffffffffu, p[j], 1);
#pragma unroll
        for (int j = 0; j < 4; j++) p[j] += __shfl_xor_sync(0xffffffffu, p[j], 2);
        if ((l & 3) == 0) {
#pragma unroll
            for (int j = 0; j < 4; j++) g_logits[(size_t)(i + j) * 8 + (l >> 2)] = p[j];
        }
#pragma unroll
        for (int j = 0; j < 4; j++) {
            float nm = fmaxf(mh, p[j]);
            dh = dh * __expf(mh - nm) + __expf(p[j] - nm);
            mh = nm;
        }
    }
    for (; i < end; i++) {
        int s0 = g_srcidx[i];
        const float4 q0 = *(const float4*)&g_P[(size_t)s0 * 256 + 4 * l];
        float ex = q0.x + dp.x, ey = q0.y + dp.y, ez = q0.z + dp.z, ew = q0.w + dp.w;
        float p0 = a0 * fmaxf(ex, 0.f) + a0q * fminf(ex, 0.f)
                 + a1 * fmaxf(ey, 0.f) + a1q * fminf(ey, 0.f)
                 + a2 * fmaxf(ez, 0.f) + a2q * fminf(ez, 0.f)
                 + a3 * fmaxf(ew, 0.f) + a3q * fminf(ew, 0.f);
        p0 += __shfl_xor_sync(0xffffffffu, p0, 1);
        p0 += __shfl_xor_sync(0xffffffffu, p0, 2);
        if ((l & 3) == 0) g_logits[(size_t)i * 8 + (l >> 2)] = p0;
        float nm = fmaxf(mh, p0);
        dh = dh * __expf(mh - nm) + __expf(p0 - nm);
        mh = nm;
    }
    if (beg < end) {
        if ((l & 3) == 0) g_md[(size_t)n * 8 + (l >> 2)] = make_float2(mh, dh);
        float m = mh;
        for (int o = 16; o; o >>= 1) m = fmaxf(m, __shfl_xor_sync(0xffffffffu, m, o));
        if (l == 0) atomicMax(&g_maxenc, encf(m));
    }
}

// ---------------- K6: softmax weights + aggregation + residual + PReLU -------
__global__ void k_aggr(const float* __restrict__ x, const float* __restrict__ bias,
                       const float* __restrict__ prelu, float* out) {
    int wid = (blockIdx.x * blockDim.x + threadIdx.x) >> 5;
    int l = threadIdx.x & 31;
    if (wid >= Nn) return;
    int n = wid;
    float M = decf(g_maxenc);
    int h = l >> 2;
    int beg = g_off[n], end = g_off[n + 1];
    float mh = 0.f, inv = 0.f;
    if (beg < end) {
        float2 md = g_md[(size_t)n * 8 + h];
        mh = md.x;
        float s = __expf(mh - M);                  // may underflow -> 0, matches ref
        inv = s / (md.y * s + 1e-16f);
    }
    float4 acc = make_float4(0.f, 0.f, 0.f, 0.f);
    int i = beg;
    for (; i + 3 < end; i += 4) {
        int s0 = g_srcidx[i],     s1 = g_srcidx[i + 1];
        int s2 = g_srcidx[i + 2], s3 = g_srcidx[i + 3];
        float l0 = g_logits[(size_t)i * 8 + h];
        float l1 = g_logits[(size_t)(i + 1) * 8 + h];
        float l2 = g_logits[(size_t)(i + 2) * 8 + h];
        float l3 = g_logits[(size_t)(i + 3) * 8 + h];
        float4 q0 = *(const float4*)&g_P[(size_t)s0 * 256 + 4 * l];
        float4 q1 = *(const float4*)&g_P[(size_t)s1 * 256 + 4 * l];
        float4 q2 = *(const float4*)&g_P[(size_t)s2 * 256 + 4 * l];
        float4 q3 = *(const float4*)&g_P[(size_t)s3 * 256 + 4 * l];
        float w0 = __expf(l0 - mh) * inv;
        float w1 = __expf(l1 - mh) * inv;
        float w2 = __expf(l2 - mh) * inv;
        float w3 = __expf(l3 - mh) * inv;
        acc.x += w0 * q0.x + w1 * q1.x + w2 * q2.x + w3 * q3.x;
        acc.y += w0 * q0.y + w1 * q1.y + w2 * q2.y + w3 * q3.y;
        acc.z += w0 * q0.z + w1 * q1.z + w2 * q2.z + w3 * q3.z;
        acc.w += w0 * q0.w + w1 * q1.w + w2 * q2.w + w3 * q3.w;
    }
    for (; i < end; i++) {
        int s0 = g_srcidx[i];
        float w0 = __expf(g_logits[(size_t)i * 8 + h] - mh) * inv;
        const float4 q0 = *(const float4*)&g_P[(size_t)s0 * 256 + 4 * l];
        acc.x += w0 * q0.x; acc.y += w0 * q0.y; acc.z += w0 * q0.z; acc.w += w0 * q0.w;
    }
    const float4 xv = *(const float4*)&x[(size_t)n * 128 + 4 * l];
    const float4 bv = *(const float4*)&bias[4 * l];
    float al = prelu[0];
    float o0 = acc.x + xv.x + bv.x; o0 = o0 > 0.f ? o0 : al * o0;
    float o1 = acc.y + xv.y + bv.y; o1 = o1 > 0.f ? o1 : al * o1;
    float o2 = acc.z + xv.z + bv.z; o2 = o2 > 0.f ? o2 : al * o2;
    float o3 = acc.w + xv.w + bv.w; o3 = o3 > 0.f ? o3 : al * o3;
    float4 ov = make_float4(o0, o1, o2, o3);
    *(float4*)&out[(size_t)n * 128 + 4 * l] = ov;
}

// ---------------- K7: readout — one block per graph --------------------------
__global__ void k_readout(const float* nodeout, const int* __restrict__ batch,
                          const float* __restrict__ ww, const float* __restrict__ bw,
                          const float* __restrict__ Wsc, const float* __restrict__ bsc,
                          float* dout) {
    __shared__ __align__(16) float Wsm[64 * 132];
    __shared__ __align__(16) float xs[8 * 128];
    __shared__ float wws[128];
    __shared__ float wghts[8];
    __shared__ float comb[256];
    __shared__ int bnds[2];
    int t = threadIdx.x;
    int g = blockIdx.x;
    if (t < 2) {   // binary search graph bounds (batch sorted)
        int tgt = g + t;
        int lo = 0, hi = Nn;
        while (lo < hi) {
            int mid = (lo + hi) >> 1;
            if (batch[mid] < tgt) lo = mid + 1; else hi = mid;
        }
        bnds[t] = lo;
    }
    if (t < 128) wws[t] = ww[t];
    __syncthreads();
    int beg = bnds[0], end = bnds[1];
    int j = t & 63, q = t >> 6;
    float bw0 = bw[0];

    for (int chh = 0; chh < 2; chh++) {
        __syncthreads();
        for (int idx = t; idx < 64 * 128; idx += 256) {
            int r = idx >> 7, k = idx & 127;
            Wsm[r * 132 + k] = Wsc[(size_t)(chh * 64 + r) * 128 + k];
        }
        int jj = chh * 64 + j;
        float bj = bsc[jj];
        float sum_j = 0.f, mx_j = -3.402823466e38f;
        for (int n0 = beg; n0 < end; n0 += 8) {
            int cnt = min(8, end - n0);
            __syncthreads();
            for (int idx = t; idx < 8 * 128; idx += 256) {
                int r = idx >> 7, k = idx & 127;
                xs[idx] = (r < cnt) ? nodeout[(size_t)(n0 + r) * 128 + k] : 0.f;
            }
            __syncthreads();
            {
                int w = t >> 5, ln = t & 31;
                float v = xs[w * 128 + ln] * wws[ln] + xs[w * 128 + ln + 32] * wws[ln + 32] +
                          xs[w * 128 + ln + 64] * wws[ln + 64] + xs[w * 128 + ln + 96] * wws[ln + 96];
                for (int o = 16; o; o >>= 1) v += __shfl_xor_sync(0xffffffffu, v, o);
                if (ln == 0) wghts[w] = (w < cnt) ? 1.f / (1.f + __expf(-(v + bw0))) : 0.f;
            }
            __syncthreads();
#pragma unroll
            for (int i2 = 0; i2 < 2; i2++) {
                int r = q * 2 + i2;
                u64 s2 = 0ull;
                for (int k = 0; k < 128; k += 8) {
                    ulonglong2 wv = *(const ulonglong2*)&Wsm[j * 132 + k];
                    ulonglong2 xv = *(const ulonglong2*)&xs[r * 128 + k];
                    ulonglong2 wv2 = *(const ulonglong2*)&Wsm[j * 132 + k + 4];
                    ulonglong2 xv2 = *(const ulonglong2*)&xs[r * 128 + k + 4];
                    fma2(s2, wv.x, xv.x); fma2(s2, wv.y, xv.y);
                    fma2(s2, wv2.x, xv2.x); fma2(s2, wv2.y, xv2.y);
                }
                float2 sp = up2(s2);
                float sc = sp.x + sp.y;
                sum_j += wghts[r] * (sc + bj);
                if (r < cnt) mx_j = fmaxf(mx_j, xs[r * 128 + jj]);
            }
        }
        __syncthreads();
        comb[t] = sum_j;
        __syncthreads();
        if (t < 64)
            dout[(size_t)Nn * 128 + g * 256 + jj] =
                comb[t] + comb[64 + t] + comb[128 + t] + comb[192 + t];
        __syncthreads();
        comb[t] = mx_j;
        __syncthreads();
        if (t < 64)
            dout[(size_t)Nn * 128 + g * 256 + 128 + jj] =
                fmaxf(fmaxf(comb[t], comb[64 + t]), fmaxf(comb[128 + t], comb[192 + t]));
    }
}

// ---------------- launch ------------------------------------------------------
extern "C" void kernel_launch(void* const* d_in, const int* in_sizes, int n_in,
                              void* d_out, int out_size) {
    const float* x     = (const float*)d_in[0];
    const int*   ei    = (const int*)d_in[1];
    const int*   batch = (const int*)d_in[2];
    const float* Wsrc  = (const float*)d_in[3];
    const float* Wdst  = (const float*)d_in[4];
    const float* attn  = (const float*)d_in[5];
    const float* bias  = (const float*)d_in[6];
    const float* prelu = (const float*)d_in[7];
    const float* ww    = (const float*)d_in[8];
    const float* bw    = (const float*)d_in[9];
    const float* Wsc   = (const float*)d_in[10];
    const float* bsc   = (const float*)d_in[11];
    float*       out   = (float*)d_out;

    k_deg<<<(Ee + 511) / 512, 512>>>(ei);        // 0
    k_scanA<<<NBLK, 256>>>();                    // 1
    k_scanB<<<1, 256>>>();                       // 2
    dim3 g1((Nn + 63) / 64, 4);
    k_proj<<<g1, 256>>>(x, Wsrc, Wdst);          // 3  <- ncu capture slot
    k_scanC<<<NBLK, 256>>>();                    // 4
    k_scatter<<<(Ee + 511) / 512, 512>>>(ei);    // 5
    k_logits<<<Nn / 8, 256>>>(attn);             // 6
    k_aggr<<<Nn / 8, 256>>>(x, bias, prelu, out);// 7
    k_readout<<<Gg, 256>>>(out, batch, ww, bw, Wsc, bsc, out); // 8
}

// round 7
// speedup vs baseline: 1.5216x; 1.5216x over previous
#include <cuda_runtime.h>
#include <cstdint>

#define Nn 50000
#define Ee 800000
#define Gg 512
#define NBLK 196   // ceil(Nn/256)

// ---------------- scratch ----------------------------------------------------
__device__ __align__(16) float  g_P[(size_t)Nn * 256];    // [N][256]: 0..127 src_p, 128..255 dst_p
__device__ __align__(16) float  g_logits[(size_t)Ee * 8];
__device__ __align__(16) int    g_deg[Nn];                // zero-init; self-cleaned each pass
__device__ __align__(16) int    g_off[Nn + 1];
__device__ __align__(16) int    g_cur[Nn];
__device__ __align__(16) int    g_srcidx[Ee];
__device__ __align__(16) int    g_part[256];
__device__ unsigned g_maxenc;   // zero-init; reset in k_scanB each pass

// ---------------- f32x2 packed helpers ---------------------------------------
typedef unsigned long long u64;
__device__ __forceinline__ u64 p2(float lo, float hi) {
    u64 r;
    asm("mov.b64 %0, {%1, %2};" : "=l"(r) : "r"(__float_as_uint(lo)), "r"(__float_as_uint(hi)));
    return r;
}
__device__ __forceinline__ void fma2(u64& d, u64 a, u64 b) {
    asm("fma.rn.f32x2 %0, %1, %2, %3;" : "=l"(d) : "l"(a), "l"(b), "l"(d));
}
__device__ __forceinline__ float2 up2(u64 v) {
    unsigned lo, hi;
    asm("mov.b64 {%0, %1}, %2;" : "=r"(lo), "=r"(hi) : "l"(v));
    return make_float2(__uint_as_float(lo), __uint_as_float(hi));
}

__device__ __forceinline__ unsigned encf(float f) {
    unsigned u = __float_as_uint(f);
    return (u & 0x80000000u) ? ~u : (u | 0x80000000u);
}
__device__ __forceinline__ float decf(unsigned e) {
    unsigned u = (e & 0x80000000u) ? (e & 0x7fffffffu) : ~e;
    return __uint_as_float(u);
}

// ---------------- K: degree histogram (g_deg pre-zeroed) ---------------------
__global__ void k_deg(const int* __restrict__ ei) {
    int e = blockIdx.x * blockDim.x + threadIdx.x;
    if (e < Ee) atomicAdd(&g_deg[ei[Ee + e]], 1);
}

// ---------------- scan A/B/C -------------------------------------------------
__global__ void k_scanA() {
    int b = blockIdx.x, t = threadIdx.x;
    int i = b * 256 + t;
    int v = (i < Nn) ? g_deg[i] : 0;
#pragma unroll
    for (int o = 16; o; o >>= 1) v += __shfl_xor_sync(0xffffffffu, v, o);
    __shared__ int sm[8];
    if ((t & 31) == 0) sm[t >> 5] = v;
    __syncthreads();
    if (t == 0) {
        int s = 0;
#pragma unroll
        for (int w = 0; w < 8; w++) s += sm[w];
        g_part[b] = s;
    }
}
__global__ void k_scanB() {
    int t = threadIdx.x;          // 256
    if (t == 0) g_maxenc = 0u;    // reset for this pass
    int v = (t < NBLK) ? g_part[t] : 0;
    int orig = v;
    int lane = t & 31, w = t >> 5;
#pragma unroll
    for (int o = 1; o < 32; o <<= 1) {
        int u = __shfl_up_sync(0xffffffffu, v, o);
        if (lane >= o) v += u;
    }
    __shared__ int wsum[8];
    if (lane == 31) wsum[w] = v;
    __syncthreads();
    if (w == 0) {
        int z = (lane < 8) ? wsum[lane] : 0;
#pragma unroll
        for (int o = 1; o < 8; o <<= 1) {
            int u = __shfl_up_sync(0xffffffffu, z, o);
            if (lane >= o) z += u;
        }
        if (lane < 8) wsum[lane] = z;
    }
    __syncthreads();
    int incl = v + (w ? wsum[w - 1] : 0);
    g_part[t] = incl - orig;
    if (t == 255) g_off[Nn] = incl;
}
__global__ void k_scanC() {
    int b = blockIdx.x, t = threadIdx.x;
    int i = b * 256 + t;
    int v = (i < Nn) ? g_deg[i] : 0;
    if (i < Nn) g_deg[i] = 0;     // self-clean for next pass
    int orig = v;
    int lane = t & 31, w = t >> 5;
#pragma unroll
    for (int o = 1; o < 32; o <<= 1) {
        int u = __shfl_up_sync(0xffffffffu, v, o);
        if (lane >= o) v += u;
    }
    __shared__ int wsum[8];
    if (lane == 31) wsum[w] = v;
    __syncthreads();
    if (w == 0) {
        int z = (lane < 8) ? wsum[lane] : 0;
#pragma unroll
        for (int o = 1; o < 8; o <<= 1) {
            int u = __shfl_up_sync(0xffffffffu, z, o);
            if (lane >= o) z += u;
        }
        if (lane < 8) wsum[lane] = z;
    }
    __syncthreads();
    int excl = v - orig + (w ? wsum[w - 1] : 0) + g_part[b];
    if (i < Nn) { g_off[i] = excl; g_cur[i] = excl; }
}

// ---------------- K1: P = x @ W^T, 128x128 tile, 8x8 micro-tile, FFMA2 -------
// grid (ceil(N/128), 2): y = matrix (0 src, 1 dst). 256 threads.
__global__ void k_proj(const float* __restrict__ x,
                       const float* __restrict__ Wsrc,
                       const float* __restrict__ Wdst) {
    __shared__ __align__(16) float xs[8][128];   // [k][row]
    __shared__ __align__(16) float ws[8][128];   // [k][col]
    int m = blockIdx.y;
    const float* W = m ? Wdst : Wsrc;
    int t  = threadIdx.x;
    int tr = t >> 4, tc = t & 15;          // 16x16 thread grid, 8x8 micro-tile
    int rb = blockIdx.x * 128;
    int lrow = t & 127, lk = (t >> 7) * 4; // loader mapping
    u64 acc[8][4];
#pragma unroll
    for (int i = 0; i < 8; i++)
#pragma unroll
        for (int j = 0; j < 4; j++) acc[i][j] = 0ull;

    for (int kc = 0; kc < 128; kc += 8) {
        __syncthreads();
        float4 xv4 = make_float4(0.f, 0.f, 0.f, 0.f);
        if (rb + lrow < Nn) xv4 = *(const float4*)&x[(size_t)(rb + lrow) * 128 + kc + lk];
        float4 wv4 = *(const float4*)&W[(size_t)lrow * 128 + kc + lk];
        xs[lk + 0][lrow] = xv4.x; xs[lk + 1][lrow] = xv4.y;
        xs[lk + 2][lrow] = xv4.z; xs[lk + 3][lrow] = xv4.w;
        ws[lk + 0][lrow] = wv4.x; ws[lk + 1][lrow] = wv4.y;
        ws[lk + 2][lrow] = wv4.z; ws[lk + 3][lrow] = wv4.w;
        __syncthreads();
#pragma unroll
        for (int kk = 0; kk < 8; kk++) {
            float4 xa = *(const float4*)&xs[kk][tr * 8];
            float4 xb = *(const float4*)&xs[kk][tr * 8 + 4];
            ulonglong2 wlo = *(const ulonglong2*)&ws[kk][tc * 8];
            ulonglong2 whi = *(const ulonglong2*)&ws[kk][tc * 8 + 4];
            float xr[8] = {xa.x, xa.y, xa.z, xa.w, xb.x, xb.y, xb.z, xb.w};
#pragma unroll
            for (int i = 0; i < 8; i++) {
                u64 xd = p2(xr[i], xr[i]);
                fma2(acc[i][0], xd, wlo.x);
                fma2(acc[i][1], xd, wlo.y);
                fma2(acc[i][2], xd, whi.x);
                fma2(acc[i][3], xd, whi.y);
            }
        }
    }
#pragma unroll
    for (int i = 0; i < 8; i++) {
        int row = rb + tr * 8 + i;
        if (row < Nn) {
            ulonglong2 v0; v0.x = acc[i][0]; v0.y = acc[i][1];
            ulonglong2 v1; v1.x = acc[i][2]; v1.y = acc[i][3];
            *(ulonglong2*)&g_P[(size_t)row * 256 + m * 128 + tc * 8]     = v0;
            *(ulonglong2*)&g_P[(size_t)row * 256 + m * 128 + tc * 8 + 4] = v1;
        }
    }
}

// ---------------- K4: scatter edges into CSR slots ---------------------------
__global__ void k_scatter(const int* __restrict__ ei) {
    int e = blockIdx.x * blockDim.x + threadIdx.x;
    if (e < Ee) {
        int d = ei[Ee + e];
        int pos = atomicAdd(&g_cur[d], 1);
        g_srcidx[pos] = ei[e];
    }
}

// ---------------- K5: logits + global max (warp/node, 2-edge unroll) ---------
__global__ void k_logits(const float* __restrict__ attn) {
    int wid = (blockIdx.x * blockDim.x + threadIdx.x) >> 5;
    int l = threadIdx.x & 31;
    if (wid >= Nn) return;
    int n = wid;
    const float4 dp = *(const float4*)&g_P[(size_t)n * 256 + 128 + 4 * l];
    float a0 = attn[4 * l], a1 = attn[4 * l + 1], a2 = attn[4 * l + 2], a3 = attn[4 * l + 3];
    float a0q = 0.2f * a0, a1q = 0.2f * a1, a2q = 0.2f * a2, a3q = 0.2f * a3;
    int beg = g_off[n], end = g_off[n + 1];
    float m = -3.402823466e38f;
    int i = beg;
    for (; i + 1 < end; i += 2) {
        int s0 = g_srcidx[i], s1 = g_srcidx[i + 1];
        const float4 q0 = *(const float4*)&g_P[(size_t)s0 * 256 + 4 * l];
        const float4 q1 = *(const float4*)&g_P[(size_t)s1 * 256 + 4 * l];
        float ex, ey, ez, ew, p0, p1;
        ex = q0.x + dp.x; ey = q0.y + dp.y; ez = q0.z + dp.z; ew = q0.w + dp.w;
        p0 = a0 * fmaxf(ex, 0.f) + a0q * fminf(ex, 0.f)
           + a1 * fmaxf(ey, 0.f) + a1q * fminf(ey, 0.f)
           + a2 * fmaxf(ez, 0.f) + a2q * fminf(ez, 0.f)
           + a3 * fmaxf(ew, 0.f) + a3q * fminf(ew, 0.f);
        ex = q1.x + dp.x; ey = q1.y + dp.y; ez = q1.z + dp.z; ew = q1.w + dp.w;
        p1 = a0 * fmaxf(ex, 0.f) + a0q * fminf(ex, 0.f)
           + a1 * fmaxf(ey, 0.f) + a1q * fminf(ey, 0.f)
           + a2 * fmaxf(ez, 0.f) + a2q * fminf(ez, 0.f)
           + a3 * fmaxf(ew, 0.f) + a3q * fminf(ew, 0.f);
        p0 += __shfl_xor_sync(0xffffffffu, p0, 1);
        p1 += __shfl_xor_sync(0xffffffffu, p1, 1);
        p0 += __shfl_xor_sync(0xffffffffu, p0, 2);
        p1 += __shfl_xor_sync(0xffffffffu, p1, 2);
        if ((l & 3) == 0) {
            g_logits[(size_t)i * 8 + (l >> 2)] = p0;
            g_logits[(size_t)(i + 1) * 8 + (l >> 2)] = p1;
        }
        m = fmaxf(m, fmaxf(p0, p1));
    }
    if (i < end) {
        int s0 = g_srcidx[i];
        const float4 q0 = *(const float4*)&g_P[(size_t)s0 * 256 + 4 * l];
        float ex = q0.x + dp.x, ey = q0.y + dp.y, ez = q0.z + dp.z, ew = q0.w + dp.w;
        float p0 = a0 * fmaxf(ex, 0.f) + a0q * fminf(ex, 0.f)
                 + a1 * fmaxf(ey, 0.f) + a1q * fminf(ey, 0.f)
                 + a2 * fmaxf(ez, 0.f) + a2q * fminf(ez, 0.f)
                 + a3 * fmaxf(ew, 0.f) + a3q * fminf(ew, 0.f);
        p0 += __shfl_xor_sync(0xffffffffu, p0, 1);
        p0 += __shfl_xor_sync(0xffffffffu, p0, 2);
        if ((l & 3) == 0) g_logits[(size_t)i * 8 + (l >> 2)] = p0;
        m = fmaxf(m, p0);
    }
    if (beg < end) {
        for (int o = 16; o; o >>= 1) m = fmaxf(m, __shfl_xor_sync(0xffffffffu, m, o));
        if (l == 0) atomicMax(&g_maxenc, encf(m));
    }
}

// ---------------- K6: softmax + aggregation + residual + PReLU ---------------
__global__ void k_aggr(const float* __restrict__ x, const float* __restrict__ bias,
                       const float* __restrict__ prelu, float* out) {
    int wid = (blockIdx.x * blockDim.x + threadIdx.x) >> 5;
    int l = threadIdx.x & 31;
    if (wid >= Nn) return;
    int n = wid;
    float M = decf(g_maxenc);
    int h = l >> 2;
    int beg = g_off[n], end = g_off[n + 1];
    float den = 0.f;
    {
        int i = beg;
        for (; i + 3 < end; i += 4) {
            float t0 = g_logits[(size_t)i * 8 + h];
            float t1 = g_logits[(size_t)(i + 1) * 8 + h];
            float t2 = g_logits[(size_t)(i + 2) * 8 + h];
            float t3 = g_logits[(size_t)(i + 3) * 8 + h];
            den += __expf(t0 - M) + __expf(t1 - M) + __expf(t2 - M) + __expf(t3 - M);
        }
        for (; i < end; i++) den += __expf(g_logits[(size_t)i * 8 + h] - M);
    }
    den += 1e-16f;
    float inv = __fdividef(1.f, den);
    float4 acc = make_float4(0.f, 0.f, 0.f, 0.f);
    int i = beg;
    for (; i + 1 < end; i += 2) {
        int s0 = g_srcidx[i], s1 = g_srcidx[i + 1];
        float w0 = __expf(g_logits[(size_t)i * 8 + h] - M) * inv;
        float w1 = __expf(g_logits[(size_t)(i + 1) * 8 + h] - M) * inv;
        const float4 q0 = *(const float4*)&g_P[(size_t)s0 * 256 + 4 * l];
        const float4 q1 = *(const float4*)&g_P[(size_t)s1 * 256 + 4 * l];
        acc.x += w0 * q0.x + w1 * q1.x;
        acc.y += w0 * q0.y + w1 * q1.y;
        acc.z += w0 * q0.z + w1 * q1.z;
        acc.w += w0 * q0.w + w1 * q1.w;
    }
    if (i < end) {
        int s0 = g_srcidx[i];
        float w0 = __expf(g_logits[(size_t)i * 8 + h] - M) * inv;
        const float4 q0 = *(const float4*)&g_P[(size_t)s0 * 256 + 4 * l];
        acc.x += w0 * q0.x; acc.y += w0 * q0.y; acc.z += w0 * q0.z; acc.w += w0 * q0.w;
    }
    const float4 xv = *(const float4*)&x[(size_t)n * 128 + 4 * l];
    const float4 bv = *(const float4*)&bias[4 * l];
    float al = prelu[0];
    float o0 = acc.x + xv.x + bv.x; o0 = o0 > 0.f ? o0 : al * o0;
    float o1 = acc.y + xv.y + bv.y; o1 = o1 > 0.f ? o1 : al * o1;
    float o2 = acc.z + xv.z + bv.z; o2 = o2 > 0.f ? o2 : al * o2;
    float o3 = acc.w + xv.w + bv.w; o3 = o3 > 0.f ? o3 : al * o3;
    float4 ov = make_float4(o0, o1, o2, o3);
    *(float4*)&out[(size_t)n * 128 + 4 * l] = ov;
}

// ---------------- K7: readout — one block per graph --------------------------
__global__ void k_readout(const float* nodeout, const int* __restrict__ batch,
                          const float* __restrict__ ww, const float* __restrict__ bw,
                          const float* __restrict__ Wsc, const float* __restrict__ bsc,
                          float* dout) {
    __shared__ __align__(16) float Wsm[64 * 132];
    __shared__ __align__(16) float xs[8 * 128];
    __shared__ float wws[128];
    __shared__ float wghts[8];
    __shared__ float comb[256];
    __shared__ int bnds[2];
    int t = threadIdx.x;
    int g = blockIdx.x;
    if (t < 2) {   // binary search graph bounds (batch sorted)
        int tgt = g + t;
        int lo = 0, hi = Nn;
        while (lo < hi) {
            int mid = (lo + hi) >> 1;
            if (batch[mid] < tgt) lo = mid + 1; else hi = mid;
        }
        bnds[t] = lo;
    }
    if (t < 128) wws[t] = ww[t];
    __syncthreads();
    int beg = bnds[0], end = bnds[1];
    int j = t & 63, q = t >> 6;
    float bw0 = bw[0];

    for (int chh = 0; chh < 2; chh++) {
        __syncthreads();
        for (int idx = t; idx < 64 * 128; idx += 256) {
            int r = idx >> 7, k = idx & 127;
            Wsm[r * 132 + k] = Wsc[(size_t)(chh * 64 + r) * 128 + k];
        }
        int jj = chh * 64 + j;
        float bj = bsc[jj];
        float sum_j = 0.f, mx_j = -3.402823466e38f;
        for (int n0 = beg; n0 < end; n0 += 8) {
            int cnt = min(8, end - n0);
            __syncthreads();
            for (int idx = t; idx < 8 * 128; idx += 256) {
                int r = idx >> 7, k = idx & 127;
                xs[idx] = (r < cnt) ? nodeout[(size_t)(n0 + r) * 128 + k] : 0.f;
            }
            __syncthreads();
            {
                int w = t >> 5, ln = t & 31;
                float v = xs[w * 128 + ln] * wws[ln] + xs[w * 128 + ln + 32] * wws[ln + 32] +
                          xs[w * 128 + ln + 64] * wws[ln + 64] + xs[w * 128 + ln + 96] * wws[ln + 96];
                for (int o = 16; o; o >>= 1) v += __shfl_xor_sync(0xffffffffu, v, o);
                if (ln == 0) wghts[w] = (w < cnt) ? 1.f / (1.f + __expf(-(v + bw0))) : 0.f;
            }
            __syncthreads();
#pragma unroll
            for (int i2 = 0; i2 < 2; i2++) {
                int r = q * 2 + i2;
                u64 s2 = 0ull;
                for (int k = 0; k < 128; k += 8) {
                    ulonglong2 wv = *(const ulonglong2*)&Wsm[j * 132 + k];
                    ulonglong2 xv = *(const ulonglong2*)&xs[r * 128 + k];
                    ulonglong2 wv2 = *(const ulonglong2*)&Wsm[j * 132 + k + 4];
                    ulonglong2 xv2 = *(const ulonglong2*)&xs[r * 128 + k + 4];
                    fma2(s2, wv.x, xv.x); fma2(s2, wv.y, xv.y);
                    fma2(s2, wv2.x, xv2.x); fma2(s2, wv2.y, xv2.y);
                }
                float2 sp = up2(s2);
                float sc = sp.x + sp.y;
                sum_j += wghts[r] * (sc + bj);
                if (r < cnt) mx_j = fmaxf(mx_j, xs[r * 128 + jj]);
            }
        }
        __syncthreads();
        comb[t] = sum_j;
        __syncthreads();
        if (t < 64)
            dout[(size_t)Nn * 128 + g * 256 + jj] =
                comb[t] + comb[64 + t] + comb[128 + t] + comb[192 + t];
        __syncthreads();
        comb[t] = mx_j;
        __syncthreads();
        if (t < 64)
            dout[(size_t)Nn * 128 + g * 256 + 128 + jj] =
                fmaxf(fmaxf(comb[t], comb[64 + t]), fmaxf(comb[128 + t], comb[192 + t]));
    }
}

// ---------------- launch ------------------------------------------------------
extern "C" void kernel_launch(void* const* d_in, const int* in_sizes, int n_in,
                              void* d_out, int out_size) {
    const float* x     = (const float*)d_in[0];
    const int*   ei    = (const int*)d_in[1];
    const int*   batch = (const int*)d_in[2];
    const float* Wsrc  = (const float*)d_in[3];
    const float* Wdst  = (const float*)d_in[4];
    const float* attn  = (const float*)d_in[5];
    const float* bias  = (const float*)d_in[6];
    const float* prelu = (const float*)d_in[7];
    const float* ww    = (const float*)d_in[8];
    const float* bw    = (const float*)d_in[9];
    const float* Wsc   = (const float*)d_in[10];
    const float* bsc   = (const float*)d_in[11];
    float*       out   = (float*)d_out;

    k_deg<<<(Ee + 511) / 512, 512>>>(ei);        // 0
    k_scanA<<<NBLK, 256>>>();                    // 1
    k_scanB<<<1, 256>>>();                       // 2
    dim3 g1((Nn + 127) / 128, 2);
    k_proj<<<g1, 256>>>(x, Wsrc, Wdst);          // 3  <- ncu capture slot
    k_scanC<<<NBLK, 256>>>();                    // 4
    k_scatter<<<(Ee + 511) / 512, 512>>>(ei);    // 5
    k_logits<<<Nn / 8, 256>>>(attn);             // 6
    k_aggr<<<Nn / 8, 256>>>(x, bias, prelu, out);// 7
    k_readout<<<Gg, 256>>>(out, batch, ww, bw, Wsc, bsc, out); // 8
}

// round 8
// speedup vs baseline: 1.7123x; 1.1253x over previous
#include <cuda_runtime.h>
#include <cstdint>

#define Nn 50000
#define Ee 800000
#define Gg 512
#define NBLK 196          // ceil(Nn/256)
#define PROJ_BLKS 782     // ceil(Nn/128) * 2
#define PROJ_BX  391
#define DEG_BLKS 391

// ---------------- scratch ----------------------------------------------------
__device__ __align__(16) float  g_P[(size_t)Nn * 256];   // [N][256]: 0..127 src_p, 128..255 dst_p
__device__ __align__(16) float  g_acc[(size_t)Nn * 128]; // unnormalized aggregation per node
__device__ __align__(16) float2 g_md[(size_t)Nn * 8];    // per (node,head): (local max, local denom)
__device__ __align__(16) int    g_deg[Nn];               // zero-init; self-cleaned
__device__ __align__(16) int    g_off[Nn + 1];
__device__ __align__(16) int    g_cur[Nn];
__device__ __align__(16) int    g_srcidx[Ee];
__device__ int      g_flag[NBLK];                        // lookback flags; self-cleaned
__device__ int      g_done;                              // self-cleaned
__device__ unsigned g_maxenc;                            // reset in k_scan

#define FLAG_A (1 << 24)
#define FLAG_P (1 << 25)
#define VALMSK 0xFFFFFF

// ---------------- f32x2 packed helpers ---------------------------------------
typedef unsigned long long u64;
__device__ __forceinline__ u64 p2(float lo, float hi) {
    u64 r;
    asm("mov.b64 %0, {%1, %2};" : "=l"(r) : "r"(__float_as_uint(lo)), "r"(__float_as_uint(hi)));
    return r;
}
__device__ __forceinline__ void fma2(u64& d, u64 a, u64 b) {
    asm("fma.rn.f32x2 %0, %1, %2, %3;" : "=l"(d) : "l"(a), "l"(b), "l"(d));
}
__device__ __forceinline__ float2 up2(u64 v) {
    unsigned lo, hi;
    asm("mov.b64 {%0, %1}, %2;" : "=r"(lo), "=r"(hi) : "l"(v));
    return make_float2(__uint_as_float(lo), __uint_as_float(hi));
}
__device__ __forceinline__ unsigned encf(float f) {
    unsigned u = __float_as_uint(f);
    return (u & 0x80000000u) ? ~u : (u | 0x80000000u);
}
__device__ __forceinline__ float decf(unsigned e) {
    unsigned u = (e & 0x80000000u) ? (e & 0x7fffffffu) : ~e;
    return __uint_as_float(u);
}

// ---------------- K1: fused projection GEMM + degree histogram ---------------
// blocks [0, PROJ_BLKS): 128x128 tile GEMM (8x8 micro-tile, FFMA2)
// blocks [PROJ_BLKS, PROJ_BLKS+DEG_BLKS): degree histogram (strided)
__global__ void k_projdeg(const float* __restrict__ x,
                          const float* __restrict__ Wsrc,
                          const float* __restrict__ Wdst,
                          const int* __restrict__ ei) {
    if (blockIdx.x >= PROJ_BLKS) {
        int bid = blockIdx.x - PROJ_BLKS;
        for (int e = bid * 256 + threadIdx.x; e < Ee; e += DEG_BLKS * 256)
            atomicAdd(&g_deg[ei[Ee + e]], 1);
        return;
    }
    __shared__ __align__(16) float xs[8][128];
    __shared__ __align__(16) float ws[8][128];
    int bx = blockIdx.x % PROJ_BX;
    int m  = blockIdx.x / PROJ_BX;
    const float* W = m ? Wdst : Wsrc;
    int t  = threadIdx.x;
    int tr = t >> 4, tc = t & 15;
    int rb = bx * 128;
    int lrow = t & 127, lk = (t >> 7) * 4;
    u64 acc[8][4];
#pragma unroll
    for (int i = 0; i < 8; i++)
#pragma unroll
        for (int j = 0; j < 4; j++) acc[i][j] = 0ull;

    for (int kc = 0; kc < 128; kc += 8) {
        __syncthreads();
        float4 xv4 = make_float4(0.f, 0.f, 0.f, 0.f);
        if (rb + lrow < Nn) xv4 = *(const float4*)&x[(size_t)(rb + lrow) * 128 + kc + lk];
        float4 wv4 = *(const float4*)&W[(size_t)lrow * 128 + kc + lk];
        xs[lk + 0][lrow] = xv4.x; xs[lk + 1][lrow] = xv4.y;
        xs[lk + 2][lrow] = xv4.z; xs[lk + 3][lrow] = xv4.w;
        ws[lk + 0][lrow] = wv4.x; ws[lk + 1][lrow] = wv4.y;
        ws[lk + 2][lrow] = wv4.z; ws[lk + 3][lrow] = wv4.w;
        __syncthreads();
#pragma unroll
        for (int kk = 0; kk < 8; kk++) {
            float4 xa = *(const float4*)&xs[kk][tr * 8];
            float4 xb = *(const float4*)&xs[kk][tr * 8 + 4];
            ulonglong2 wlo = *(const ulonglong2*)&ws[kk][tc * 8];
            ulonglong2 whi = *(const ulonglong2*)&ws[kk][tc * 8 + 4];
            float xr[8] = {xa.x, xa.y, xa.z, xa.w, xb.x, xb.y, xb.z, xb.w};
#pragma unroll
            for (int i = 0; i < 8; i++) {
                u64 xd = p2(xr[i], xr[i]);
                fma2(acc[i][0], xd, wlo.x);
                fma2(acc[i][1], xd, wlo.y);
                fma2(acc[i][2], xd, whi.x);
                fma2(acc[i][3], xd, whi.y);
            }
        }
    }
#pragma unroll
    for (int i = 0; i < 8; i++) {
        int row = rb + tr * 8 + i;
        if (row < Nn) {
            ulonglong2 v0; v0.x = acc[i][0]; v0.y = acc[i][1];
            ulonglong2 v1; v1.x = acc[i][2]; v1.y = acc[i][3];
            *(ulonglong2*)&g_P[(size_t)row * 256 + m * 128 + tc * 8]     = v0;
            *(ulonglong2*)&g_P[(size_t)row * 256 + m * 128 + tc * 8 + 4] = v1;
        }
    }
}

// ---------------- K2: single-kernel decoupled-lookback exclusive scan --------
__global__ void k_scan() {
    int b = blockIdx.x, t = threadIdx.x;
    int i = b * 256 + t;
    int v = (i < Nn) ? g_deg[i] : 0;
    if (i < Nn) g_deg[i] = 0;      // self-clean for next replay
    if (b == 0 && t == 1) g_maxenc = 0u;
    // block inclusive scan
    int lane = t & 31, w = t >> 5;
    int incl = v;
#pragma unroll
    for (int o = 1; o < 32; o <<= 1) {
        int u = __shfl_up_sync(0xffffffffu, incl, o);
        if (lane >= o) incl += u;
    }
    __shared__ int wsum[8];
    if (lane == 31) wsum[w] = incl;
    __syncthreads();
    if (w == 0) {
        int z = (lane < 8) ? wsum[lane] : 0;
#pragma unroll
        for (int o = 1; o < 8; o <<= 1) {
            int u = __shfl_up_sync(0xffffffffu, z, o);
            if (lane >= o) z += u;
        }
        if (lane < 8) wsum[lane] = z;
    }
    __syncthreads();
    incl += (w ? wsum[w - 1] : 0);
    __shared__ int blksum_s, prev_s;
    if (t == 255) blksum_s = incl;
    __syncthreads();
    int blksum = blksum_s;
    if (t == 0) {
        int prev = 0;
        if (b == 0) {
            atomicExch(&g_flag[0], FLAG_P | blksum);
        } else {
            atomicExch(&g_flag[b], FLAG_A | blksum);
            int j = b - 1;
            while (true) {
                int f;
                do { f = *(volatile int*)&g_flag[j]; } while (f == 0);
                prev += f & VALMSK;
                if (f & FLAG_P) break;
                j--;
            }
            atomicExch(&g_flag[b], FLAG_P | (prev + blksum));
        }
        prev_s = prev;
    }
    __syncthreads();
    int excl = prev_s + incl - v;
    if (i < Nn) { g_off[i] = excl; g_cur[i] = excl; }
    if (b == NBLK - 1 && t == 255) g_off[Nn] = prev_s + incl;
    // self-clean flags once all blocks are done
    if (t == 0) {
        int d = atomicAdd(&g_done, 1);
        if (d == NBLK - 1) {
            for (int j = 0; j < NBLK; j++) g_flag[j] = 0;
            g_done = 0;
        }
    }
}

// ---------------- K3: scatter edges into CSR slots ---------------------------
__global__ void k_scatter(const int* __restrict__ ei) {
    int e = blockIdx.x * blockDim.x + threadIdx.x;
    if (e < Ee) {
        int d = ei[Ee + e];
        int pos = atomicAdd(&g_cur[d], 1);
        g_srcidx[pos] = ei[e];
    }
}

// ---------------- K4: fused logits + online-softmax aggregation --------------
// one warp per dst node; lane l owns channels [4l,4l+4); head h = l>>2
__global__ void k_edge(const float* __restrict__ attn) {
    int wid = (blockIdx.x * blockDim.x + threadIdx.x) >> 5;
    int l = threadIdx.x & 31;
    if (wid >= Nn) return;
    int n = wid;
    const float4 dp = *(const float4*)&g_P[(size_t)n * 256 + 128 + 4 * l];
    float a0 = attn[4 * l], a1 = attn[4 * l + 1], a2 = attn[4 * l + 2], a3 = attn[4 * l + 3];
    float a0q = 0.2f * a0, a1q = 0.2f * a1, a2q = 0.2f * a2, a3q = 0.2f * a3;
    int beg = g_off[n], end = g_off[n + 1];
    float mh = -3.402823466e38f;  // per-head running max (quad-duplicated)
    float dh = 0.f;               // per-head running denom
    float4 acc = make_float4(0.f, 0.f, 0.f, 0.f);
    int i = beg;
    for (; i + 3 < end; i += 4) {
        int s0 = g_srcidx[i],     s1 = g_srcidx[i + 1];
        int s2 = g_srcidx[i + 2], s3 = g_srcidx[i + 3];
        float4 q0 = *(const float4*)&g_P[(size_t)s0 * 256 + 4 * l];
        float4 q1 = *(const float4*)&g_P[(size_t)s1 * 256 + 4 * l];
        float4 q2 = *(const float4*)&g_P[(size_t)s2 * 256 + 4 * l];
        float4 q3 = *(const float4*)&g_P[(size_t)s3 * 256 + 4 * l];
        float p0, p1, p2, p3;
        {
            float ex = q0.x + dp.x, ey = q0.y + dp.y, ez = q0.z + dp.z, ew = q0.w + dp.w;
            p0 = a0 * fmaxf(ex, 0.f) + a0q * fminf(ex, 0.f)
               + a1 * fmaxf(ey, 0.f) + a1q * fminf(ey, 0.f)
               + a2 * fmaxf(ez, 0.f) + a2q * fminf(ez, 0.f)
               + a3 * fmaxf(ew, 0.f) + a3q * fminf(ew, 0.f);
            ex = q1.x + dp.x; ey = q1.y + dp.y; ez = q1.z + dp.z; ew = q1.w + dp.w;
            p1 = a0 * fmaxf(ex, 0.f) + a0q * fminf(ex, 0.f)
               + a1 * fmaxf(ey, 0.f) + a1q * fminf(ey, 0.f)
               + a2 * fmaxf(ez, 0.f) + a2q * fminf(ez, 0.f)
               + a3 * fmaxf(ew, 0.f) + a3q * fminf(ew, 0.f);
            ex = q2.x + dp.x; ey = q2.y + dp.y; ez = q2.z + dp.z; ew = q2.w + dp.w;
            p2 = a0 * fmaxf(ex, 0.f) + a0q * fminf(ex, 0.f)
               + a1 * fmaxf(ey, 0.f) + a1q * fminf(ey, 0.f)
               + a2 * fmaxf(ez, 0.f) + a2q * fminf(ez, 0.f)
               + a3 * fmaxf(ew, 0.f) + a3q * fminf(ew, 0.f);
            ex = q3.x + dp.x; ey = q3.y + dp.y; ez = q3.z + dp.z; ew = q3.w + dp.w;
            p3 = a0 * fmaxf(ex, 0.f) + a0q * fminf(ex, 0.f)
               + a1 * fmaxf(ey, 0.f) + a1q * fminf(ey, 0.f)
               + a2 * fmaxf(ez, 0.f) + a2q * fminf(ez, 0.f)
               + a3 * fmaxf(ew, 0.f) + a3q * fminf(ew, 0.f);
        }
        p0 += __shfl_xor_sync(0xffffffffu, p0, 1);
        p1 += __shfl_xor_sync(0xffffffffu, p1, 1);
        p2 += __shfl_xor_sync(0xffffffffu, p2, 1);
        p3 += __shfl_xor_sync(0xffffffffu, p3, 1);
        p0 += __shfl_xor_sync(0xffffffffu, p0, 2);
        p1 += __shfl_xor_sync(0xffffffffu, p1, 2);
        p2 += __shfl_xor_sync(0xffffffffu, p2, 2);
        p3 += __shfl_xor_sync(0xffffffffu, p3, 2);
        float gm = fmaxf(fmaxf(p0, p1), fmaxf(p2, p3));
        float nm = fmaxf(mh, gm);
        float r  = __expf(mh - nm);
        float w0 = __expf(p0 - nm), w1 = __expf(p1 - nm);
        float w2 = __expf(p2 - nm), w3 = __expf(p3 - nm);
        dh = dh * r + (w0 + w1 + w2 + w3);
        acc.x = acc.x * r + w0 * q0.x + w1 * q1.x + w2 * q2.x + w3 * q3.x;
        acc.y = acc.y * r + w0 * q0.y + w1 * q1.y + w2 * q2.y + w3 * q3.y;
        acc.z = acc.z * r + w0 * q0.z + w1 * q1.z + w2 * q2.z + w3 * q3.z;
        acc.w = acc.w * r + w0 * q0.w + w1 * q1.w + w2 * q2.w + w3 * q3.w;
        mh = nm;
    }
    for (; i < end; i++) {
        int s0 = g_srcidx[i];
        float4 q0 = *(const float4*)&g_P[(size_t)s0 * 256 + 4 * l];
        float ex = q0.x + dp.x, ey = q0.y + dp.y, ez = q0.z + dp.z, ew = q0.w + dp.w;
        float p0 = a0 * fmaxf(ex, 0.f) + a0q * fminf(ex, 0.f)
                 + a1 * fmaxf(ey, 0.f) + a1q * fminf(ey, 0.f)
                 + a2 * fmaxf(ez, 0.f) + a2q * fminf(ez, 0.f)
                 + a3 * fmaxf(ew, 0.f) + a3q * fminf(ew, 0.f);
        p0 += __shfl_xor_sync(0xffffffffu, p0, 1);
        p0 += __shfl_xor_sync(0xffffffffu, p0, 2);
        float nm = fmaxf(mh, p0);
        float r  = __expf(mh - nm);
        float w0 = __expf(p0 - nm);
        dh = dh * r + w0;
        acc.x = acc.x * r + w0 * q0.x;
        acc.y = acc.y * r + w0 * q0.y;
        acc.z = acc.z * r + w0 * q0.z;
        acc.w = acc.w * r + w0 * q0.w;
        mh = nm;
    }
    if (beg < end) {
        *(float4*)&g_acc[(size_t)n * 128 + 4 * l] = acc;
        if ((l & 3) == 0) g_md[(size_t)n * 8 + (l >> 2)] = make_float2(mh, dh);
        float m = mh;
        for (int o = 16; o; o >>= 1) m = fmaxf(m, __shfl_xor_sync(0xffffffffu, m, o));
        if (l == 0) atomicMax(&g_maxenc, encf(m));
    }
}

// ---------------- K5: finalize — normalize + residual + PReLU ----------------
__global__ void k_fin(const float* __restrict__ x, const float* __restrict__ bias,
                      const float* __restrict__ prelu, float* out) {
    int wid = (blockIdx.x * blockDim.x + threadIdx.x) >> 5;
    int l = threadIdx.x & 31;
    if (wid >= Nn) return;
    int n = wid;
    int beg = g_off[n], end = g_off[n + 1];
    float4 acc = make_float4(0.f, 0.f, 0.f, 0.f);
    float f = 0.f;
    if (beg < end) {
        float M = decf(g_maxenc);
        float2 md = g_md[(size_t)n * 8 + (l >> 2)];
        float s = __expf(md.x - M);            // s <= 1 (mh <= M)
        f = s / (s * md.y + 1e-16f);
        acc = *(const float4*)&g_acc[(size_t)n * 128 + 4 * l];
    }
    const float4 xv = *(const float4*)&x[(size_t)n * 128 + 4 * l];
    const float4 bv = *(const float4*)&bias[4 * l];
    float al = prelu[0];
    float o0 = acc.x * f + xv.x + bv.x; o0 = o0 > 0.f ? o0 : al * o0;
    float o1 = acc.y * f + xv.y + bv.y; o1 = o1 > 0.f ? o1 : al * o1;
    float o2 = acc.z * f + xv.z + bv.z; o2 = o2 > 0.f ? o2 : al * o2;
    float o3 = acc.w * f + xv.w + bv.w; o3 = o3 > 0.f ? o3 : al * o3;
    *(float4*)&out[(size_t)n * 128 + 4 * l] = make_float4(o0, o1, o2, o3);
}

// ---------------- K6: readout — one block per graph --------------------------
__global__ void k_readout(const float* nodeout, const int* __restrict__ batch,
                          const float* __restrict__ ww, const float* __restrict__ bw,
                          const float* __restrict__ Wsc, const float* __restrict__ bsc,
                          float* dout) {
    __shared__ __align__(16) float Wsm[64 * 132];
    __shared__ __align__(16) float xs[8 * 128];
    __shared__ float wws[128];
    __shared__ float wghts[8];
    __shared__ float comb[256];
    __shared__ int bnds[2];
    int t = threadIdx.x;
    int g = blockIdx.x;
    if (t < 2) {
        int tgt = g + t;
        int lo = 0, hi = Nn;
        while (lo < hi) {
            int mid = (lo + hi) >> 1;
            if (batch[mid] < tgt) lo = mid + 1; else hi = mid;
        }
        bnds[t] = lo;
    }
    if (t < 128) wws[t] = ww[t];
    __syncthreads();
    int beg = bnds[0], end = bnds[1];
    int j = t & 63, q = t >> 6;
    float bw0 = bw[0];

    for (int chh = 0; chh < 2; chh++) {
        __syncthreads();
        for (int idx = t; idx < 64 * 128; idx += 256) {
            int r = idx >> 7, k = idx & 127;
            Wsm[r * 132 + k] = Wsc[(size_t)(chh * 64 + r) * 128 + k];
        }
        int jj = chh * 64 + j;
        float bj = bsc[jj];
        float sum_j = 0.f, mx_j = -3.402823466e38f;
        for (int n0 = beg; n0 < end; n0 += 8) {
            int cnt = min(8, end - n0);
            __syncthreads();
            for (int idx = t; idx < 8 * 128; idx += 256) {
                int r = idx >> 7, k = idx & 127;
                xs[idx] = (r < cnt) ? nodeout[(size_t)(n0 + r) * 128 + k] : 0.f;
            }
            __syncthreads();
            {
                int w = t >> 5, ln = t & 31;
                float v = xs[w * 128 + ln] * wws[ln] + xs[w * 128 + ln + 32] * wws[ln + 32] +
                          xs[w * 128 + ln + 64] * wws[ln + 64] + xs[w * 128 + ln + 96] * wws[ln + 96];
                for (int o = 16; o; o >>= 1) v += __shfl_xor_sync(0xffffffffu, v, o);
                if (ln == 0) wghts[w] = (w < cnt) ? 1.f / (1.f + __expf(-(v + bw0))) : 0.f;
            }
            __syncthreads();
#pragma unroll
            for (int i2 = 0; i2 < 2; i2++) {
                int r = q * 2 + i2;
                u64 s2 = 0ull;
                for (int k = 0; k < 128; k += 8) {
                    ulonglong2 wv = *(const ulonglong2*)&Wsm[j * 132 + k];
                    ulonglong2 xv = *(const ulonglong2*)&xs[r * 128 + k];
                    ulonglong2 wv2 = *(const ulonglong2*)&Wsm[j * 132 + k + 4];
                    ulonglong2 xv2 = *(const ulonglong2*)&xs[r * 128 + k + 4];
                    fma2(s2, wv.x, xv.x); fma2(s2, wv.y, xv.y);
                    fma2(s2, wv2.x, xv2.x); fma2(s2, wv2.y, xv2.y);
                }
                float2 sp = up2(s2);
                float sc = sp.x + sp.y;
                sum_j += wghts[r] * (sc + bj);
                if (r < cnt) mx_j = fmaxf(mx_j, xs[r * 128 + jj]);
            }
        }
        __syncthreads();
        comb[t] = sum_j;
        __syncthreads();
        if (t < 64)
            dout[(size_t)Nn * 128 + g * 256 + jj] =
                comb[t] + comb[64 + t] + comb[128 + t] + comb[192 + t];
        __syncthreads();
        comb[t] = mx_j;
        __syncthreads();
        if (t < 64)
            dout[(size_t)Nn * 128 + g * 256 + 128 + jj] =
                fmaxf(fmaxf(comb[t], comb[64 + t]), fmaxf(comb[128 + t], comb[192 + t]));
    }
}

// ---------------- launch ------------------------------------------------------
extern "C" void kernel_launch(void* const* d_in, const int* in_sizes, int n_in,
                              void* d_out, int out_size) {
    const float* x     = (const float*)d_in[0];
    const int*   ei    = (const int*)d_in[1];
    const int*   batch = (const int*)d_in[2];
    const float* Wsrc  = (const float*)d_in[3];
    const float* Wdst  = (const float*)d_in[4];
    const float* attn  = (const float*)d_in[5];
    const float* bias  = (const float*)d_in[6];
    const float* prelu = (const float*)d_in[7];
    const float* ww    = (const float*)d_in[8];
    const float* bw    = (const float*)d_in[9];
    const float* Wsc   = (const float*)d_in[10];
    const float* bsc   = (const float*)d_in[11];
    float*       out   = (float*)d_out;

    k_projdeg<<<PROJ_BLKS + DEG_BLKS, 256>>>(x, Wsrc, Wdst, ei);   // 0
    k_scan<<<NBLK, 256>>>();                                       // 1
    k_scatter<<<(Ee + 511) / 512, 512>>>(ei);                      // 2
    k_edge<<<Nn / 8, 256>>>(attn);                                 // 3 <- ncu slot
    k_fin<<<Nn / 8, 256>>>(x, bias, prelu, out);                   // 4
    k_readout<<<Gg, 256>>>(out, batch, ww, bw, Wsc, bsc, out);     // 5
}

// round 9
// speedup vs baseline: 2.1365x; 1.2478x over previous
#include <cuda_runtime.h>
#include <cstdint>

#define Nn 50000
#define Ee 800000
#define Gg 512
#define NBLK 196          // ceil(Nn/256)
#define PROJ_BLKS 782     // ceil(Nn/128) * 2
#define PROJ_BX  391
#define DEG_BLKS 391

// ---------------- scratch ----------------------------------------------------
__device__ __align__(16) float  g_P[(size_t)Nn * 256];    // [N][256]: 0..127 src_p, 128..255 dst_p
__device__ __align__(16) float  g_acc[(size_t)Nn * 128];  // unnormalized aggregation
__device__ __align__(16) float  g_score[(size_t)Nn * 128];// out @ Wsc^T
__device__ __align__(16) float2 g_md[(size_t)Nn * 8];     // per (node,head): (max, denom)
__device__ __align__(16) int    g_deg[Nn];                // zero-init; self-cleaned
__device__ __align__(16) int    g_off[Nn + 1];
__device__ __align__(16) int    g_cur[Nn];
__device__ __align__(16) int    g_srcidx[Ee];
__device__ int      g_flag[NBLK];
__device__ int      g_done;
__device__ unsigned g_maxenc;

#define FLAG_A (1 << 24)
#define FLAG_P (1 << 25)
#define VALMSK 0xFFFFFF

// ---------------- f32x2 packed helpers ---------------------------------------
typedef unsigned long long u64;
__device__ __forceinline__ u64 p2(float lo, float hi) {
    u64 r;
    asm("mov.b64 %0, {%1, %2};" : "=l"(r) : "r"(__float_as_uint(lo)), "r"(__float_as_uint(hi)));
    return r;
}
__device__ __forceinline__ void fma2(u64& d, u64 a, u64 b) {
    asm("fma.rn.f32x2 %0, %1, %2, %3;" : "=l"(d) : "l"(a), "l"(b), "l"(d));
}
__device__ __forceinline__ unsigned encf(float f) {
    unsigned u = __float_as_uint(f);
    return (u & 0x80000000u) ? ~u : (u | 0x80000000u);
}
__device__ __forceinline__ float decf(unsigned e) {
    unsigned u = (e & 0x80000000u) ? (e & 0x7fffffffu) : ~e;
    return __uint_as_float(u);
}

// ---------------- K1: fused projection GEMM + degree histogram ---------------
__global__ void k_projdeg(const float* __restrict__ x,
                          const float* __restrict__ Wsrc,
                          const float* __restrict__ Wdst,
                          const int* __restrict__ ei) {
    if (blockIdx.x >= PROJ_BLKS) {
        int bid = blockIdx.x - PROJ_BLKS;
        for (int e = bid * 256 + threadIdx.x; e < Ee; e += DEG_BLKS * 256)
            atomicAdd(&g_deg[ei[Ee + e]], 1);
        return;
    }
    __shared__ __align__(16) float xs[8][128];
    __shared__ __align__(16) float ws[8][128];
    int bx = blockIdx.x % PROJ_BX;
    int m  = blockIdx.x / PROJ_BX;
    const float* W = m ? Wdst : Wsrc;
    int t  = threadIdx.x;
    int tr = t >> 4, tc = t & 15;
    int rb = bx * 128;
    int lrow = t & 127, lk = (t >> 7) * 4;
    u64 acc[8][4];
#pragma unroll
    for (int i = 0; i < 8; i++)
#pragma unroll
        for (int j = 0; j < 4; j++) acc[i][j] = 0ull;

    for (int kc = 0; kc < 128; kc += 8) {
        __syncthreads();
        float4 xv4 = make_float4(0.f, 0.f, 0.f, 0.f);
        if (rb + lrow < Nn) xv4 = *(const float4*)&x[(size_t)(rb + lrow) * 128 + kc + lk];
        float4 wv4 = *(const float4*)&W[(size_t)lrow * 128 + kc + lk];
        xs[lk + 0][lrow] = xv4.x; xs[lk + 1][lrow] = xv4.y;
        xs[lk + 2][lrow] = xv4.z; xs[lk + 3][lrow] = xv4.w;
        ws[lk + 0][lrow] = wv4.x; ws[lk + 1][lrow] = wv4.y;
        ws[lk + 2][lrow] = wv4.z; ws[lk + 3][lrow] = wv4.w;
        __syncthreads();
#pragma unroll
        for (int kk = 0; kk < 8; kk++) {
            float4 xa = *(const float4*)&xs[kk][tr * 8];
            float4 xb = *(const float4*)&xs[kk][tr * 8 + 4];
            ulonglong2 wlo = *(const ulonglong2*)&ws[kk][tc * 8];
            ulonglong2 whi = *(const ulonglong2*)&ws[kk][tc * 8 + 4];
            float xr[8] = {xa.x, xa.y, xa.z, xa.w, xb.x, xb.y, xb.z, xb.w};
#pragma unroll
            for (int i = 0; i < 8; i++) {
                u64 xd = p2(xr[i], xr[i]);
                fma2(acc[i][0], xd, wlo.x);
                fma2(acc[i][1], xd, wlo.y);
                fma2(acc[i][2], xd, whi.x);
                fma2(acc[i][3], xd, whi.y);
            }
        }
    }
#pragma unroll
    for (int i = 0; i < 8; i++) {
        int row = rb + tr * 8 + i;
        if (row < Nn) {
            ulonglong2 v0; v0.x = acc[i][0]; v0.y = acc[i][1];
            ulonglong2 v1; v1.x = acc[i][2]; v1.y = acc[i][3];
            *(ulonglong2*)&g_P[(size_t)row * 256 + m * 128 + tc * 8]     = v0;
            *(ulonglong2*)&g_P[(size_t)row * 256 + m * 128 + tc * 8 + 4] = v1;
        }
    }
}

// ---------------- K2: decoupled-lookback exclusive scan ----------------------
__global__ void k_scan() {
    int b = blockIdx.x, t = threadIdx.x;
    int i = b * 256 + t;
    int v = (i < Nn) ? g_deg[i] : 0;
    if (i < Nn) g_deg[i] = 0;
    if (b == 0 && t == 1) g_maxenc = 0u;
    int lane = t & 31, w = t >> 5;
    int incl = v;
#pragma unroll
    for (int o = 1; o < 32; o <<= 1) {
        int u = __shfl_up_sync(0xffffffffu, incl, o);
        if (lane >= o) incl += u;
    }
    __shared__ int wsum[8];
    if (lane == 31) wsum[w] = incl;
    __syncthreads();
    if (w == 0) {
        int z = (lane < 8) ? wsum[lane] : 0;
#pragma unroll
        for (int o = 1; o < 8; o <<= 1) {
            int u = __shfl_up_sync(0xffffffffu, z, o);
            if (lane >= o) z += u;
        }
        if (lane < 8) wsum[lane] = z;
    }
    __syncthreads();
    incl += (w ? wsum[w - 1] : 0);
    __shared__ int blksum_s, prev_s;
    if (t == 255) blksum_s = incl;
    __syncthreads();
    int blksum = blksum_s;
    if (t == 0) {
        int prev = 0;
        if (b == 0) {
            atomicExch(&g_flag[0], FLAG_P | blksum);
        } else {
            atomicExch(&g_flag[b], FLAG_A | blksum);
            int j = b - 1;
            while (true) {
                int f;
                do { f = *(volatile int*)&g_flag[j]; } while (f == 0);
                prev += f & VALMSK;
                if (f & FLAG_P) break;
                j--;
            }
            atomicExch(&g_flag[b], FLAG_P | (prev + blksum));
        }
        prev_s = prev;
    }
    __syncthreads();
    int excl = prev_s + incl - v;
    if (i < Nn) { g_off[i] = excl; g_cur[i] = excl; }
    if (b == NBLK - 1 && t == 255) g_off[Nn] = prev_s + incl;
    if (t == 0) {
        int d = atomicAdd(&g_done, 1);
        if (d == NBLK - 1) {
            for (int j = 0; j < NBLK; j++) g_flag[j] = 0;
            g_done = 0;
        }
    }
}

// ---------------- K3: scatter edges into CSR slots ---------------------------
__global__ void k_scatter(const int* __restrict__ ei) {
    int e = blockIdx.x * blockDim.x + threadIdx.x;
    if (e < Ee) {
        int d = ei[Ee + e];
        int pos = atomicAdd(&g_cur[d], 1);
        g_srcidx[pos] = ei[e];
    }
}

// ---------------- K4: fused logits + online-softmax aggregation --------------
__global__ void k_edge(const float* __restrict__ attn) {
    int wid = (blockIdx.x * blockDim.x + threadIdx.x) >> 5;
    int l = threadIdx.x & 31;
    if (wid >= Nn) return;
    int n = wid;
    const float4 dp = *(const float4*)&g_P[(size_t)n * 256 + 128 + 4 * l];
    float a0 = attn[4 * l], a1 = attn[4 * l + 1], a2 = attn[4 * l + 2], a3 = attn[4 * l + 3];
    float a0q = 0.2f * a0, a1q = 0.2f * a1, a2q = 0.2f * a2, a3q = 0.2f * a3;
    int beg = g_off[n], end = g_off[n + 1];
    float mh = -3.402823466e38f;
    float dh = 0.f;
    float4 acc = make_float4(0.f, 0.f, 0.f, 0.f);
    int i = beg;
    for (; i + 3 < end; i += 4) {
        int s0 = g_srcidx[i],     s1 = g_srcidx[i + 1];
        int s2 = g_srcidx[i + 2], s3 = g_srcidx[i + 3];
        float4 q0 = *(const float4*)&g_P[(size_t)s0 * 256 + 4 * l];
        float4 q1 = *(const float4*)&g_P[(size_t)s1 * 256 + 4 * l];
        float4 q2 = *(const float4*)&g_P[(size_t)s2 * 256 + 4 * l];
        float4 q3 = *(const float4*)&g_P[(size_t)s3 * 256 + 4 * l];
        float p0, p1, p2, p3;
        {
            float ex = q0.x + dp.x, ey = q0.y + dp.y, ez = q0.z + dp.z, ew = q0.w + dp.w;
            p0 = a0 * fmaxf(ex, 0.f) + a0q * fminf(ex, 0.f)
               + a1 * fmaxf(ey, 0.f) + a1q * fminf(ey, 0.f)
               + a2 * fmaxf(ez, 0.f) + a2q * fminf(ez, 0.f)
               + a3 * fmaxf(ew, 0.f) + a3q * fminf(ew, 0.f);
            ex = q1.x + dp.x; ey = q1.y + dp.y; ez = q1.z + dp.z; ew = q1.w + dp.w;
            p1 = a0 * fmaxf(ex, 0.f) + a0q * fminf(ex, 0.f)
               + a1 * fmaxf(ey, 0.f) + a1q * fminf(ey, 0.f)
               + a2 * fmaxf(ez, 0.f) + a2q * fminf(ez, 0.f)
               + a3 * fmaxf(ew, 0.f) + a3q * fminf(ew, 0.f);
            ex = q2.x + dp.x; ey = q2.y + dp.y; ez = q2.z + dp.z; ew = q2.w + dp.w;
            p2 = a0 * fmaxf(ex, 0.f) + a0q * fminf(ex, 0.f)
               + a1 * fmaxf(ey, 0.f) + a1q * fminf(ey, 0.f)
               + a2 * fmaxf(ez, 0.f) + a2q * fminf(ez, 0.f)
               + a3 * fmaxf(ew, 0.f) + a3q * fminf(ew, 0.f);
            ex = q3.x + dp.x; ey = q3.y + dp.y; ez = q3.z + dp.z; ew = q3.w + dp.w;
            p3 = a0 * fmaxf(ex, 0.f) + a0q * fminf(ex, 0.f)
               + a1 * fmaxf(ey, 0.f) + a1q * fminf(ey, 0.f)
               + a2 * fmaxf(ez, 0.f) + a2q * fminf(ez, 0.f)
               + a3 * fmaxf(ew, 0.f) + a3q * fminf(ew, 0.f);
        }
        p0 += __shfl_xor_sync(0xffffffffu, p0, 1);
        p1 += __shfl_xor_sync(0xffffffffu, p1, 1);
        p2 += __shfl_xor_sync(0xffffffffu, p2, 1);
        p3 += __shfl_xor_sync(0xffffffffu, p3, 1);
        p0 += __shfl_xor_sync(0xffffffffu, p0, 2);
        p1 += __shfl_xor_sync(0xffffffffu, p1, 2);
        p2 += __shfl_xor_sync(0xffffffffu, p2, 2);
        p3 += __shfl_xor_sync(0xffffffffu, p3, 2);
        float gm = fmaxf(fmaxf(p0, p1), fmaxf(p2, p3));
        float nm = fmaxf(mh, gm);
        float r  = __expf(mh - nm);
        float w0 = __expf(p0 - nm), w1 = __expf(p1 - nm);
        float w2 = __expf(p2 - nm), w3 = __expf(p3 - nm);
        dh = dh * r + (w0 + w1 + w2 + w3);
        acc.x = acc.x * r + w0 * q0.x + w1 * q1.x + w2 * q2.x + w3 * q3.x;
        acc.y = acc.y * r + w0 * q0.y + w1 * q1.y + w2 * q2.y + w3 * q3.y;
        acc.z = acc.z * r + w0 * q0.z + w1 * q1.z + w2 * q2.z + w3 * q3.z;
        acc.w = acc.w * r + w0 * q0.w + w1 * q1.w + w2 * q2.w + w3 * q3.w;
        mh = nm;
    }
    for (; i < end; i++) {
        int s0 = g_srcidx[i];
        float4 q0 = *(const float4*)&g_P[(size_t)s0 * 256 + 4 * l];
        float ex = q0.x + dp.x, ey = q0.y + dp.y, ez = q0.z + dp.z, ew = q0.w + dp.w;
        float p0 = a0 * fmaxf(ex, 0.f) + a0q * fminf(ex, 0.f)
                 + a1 * fmaxf(ey, 0.f) + a1q * fminf(ey, 0.f)
                 + a2 * fmaxf(ez, 0.f) + a2q * fminf(ez, 0.f)
                 + a3 * fmaxf(ew, 0.f) + a3q * fminf(ew, 0.f);
        p0 += __shfl_xor_sync(0xffffffffu, p0, 1);
        p0 += __shfl_xor_sync(0xffffffffu, p0, 2);
        float nm = fmaxf(mh, p0);
        float r  = __expf(mh - nm);
        float w0 = __expf(p0 - nm);
        dh = dh * r + w0;
        acc.x = acc.x * r + w0 * q0.x;
        acc.y = acc.y * r + w0 * q0.y;
        acc.z = acc.z * r + w0 * q0.z;
        acc.w = acc.w * r + w0 * q0.w;
        mh = nm;
    }
    *(float4*)&g_acc[(size_t)n * 128 + 4 * l] = acc;   // empty node: zeros, mh=-inf
    if ((l & 3) == 0) g_md[(size_t)n * 8 + (l >> 2)] = make_float2(mh, dh);
    if (beg < end) {
        float m = mh;
        for (int o = 16; o; o >>= 1) m = fmaxf(m, __shfl_xor_sync(0xffffffffu, m, o));
        if (l == 0) atomicMax(&g_maxenc, encf(m));
    }
}

// ---------------- K5: fused finalize + score GEMM ----------------------------
// loader computes out = PReLU(acc*f + x + bias), writes it to global, stages in
// smem; GEMM computes score = out @ Wsc^T into g_score.
__global__ void k_score(const float* __restrict__ x, const float* __restrict__ bias,
                        const float* __restrict__ prelu, const float* __restrict__ Wsc,
                        float* out) {
    __shared__ __align__(16) float xs[8][128];
    __shared__ __align__(16) float ws[8][128];
    int t  = threadIdx.x;
    int tr = t >> 4, tc = t & 15;
    int rb = blockIdx.x * 128;
    int lrow = t & 127, lk = (t >> 7) * 4;
    float al = prelu[0];
    float M = decf(g_maxenc);
    u64 acc[8][4];
#pragma unroll
    for (int i = 0; i < 8; i++)
#pragma unroll
        for (int j = 0; j < 4; j++) acc[i][j] = 0ull;

    for (int kc = 0; kc < 128; kc += 8) {
        __syncthreads();
        int row = rb + lrow;
        int k = kc + lk;
        float4 o4 = make_float4(0.f, 0.f, 0.f, 0.f);
        if (row < Nn) {
            float4 a4 = *(const float4*)&g_acc[(size_t)row * 128 + k];
            float2 md = g_md[(size_t)row * 8 + (k >> 4)];
            float s = __expf(md.x - M);
            float f = s / (s * md.y + 1e-16f);
            float4 x4 = *(const float4*)&x[(size_t)row * 128 + k];
            float4 b4 = *(const float4*)&bias[k];
            o4.x = a4.x * f + x4.x + b4.x; o4.x = o4.x > 0.f ? o4.x : al * o4.x;
            o4.y = a4.y * f + x4.y + b4.y; o4.y = o4.y > 0.f ? o4.y : al * o4.y;
            o4.z = a4.z * f + x4.z + b4.z; o4.z = o4.z > 0.f ? o4.z : al * o4.z;
            o4.w = a4.w * f + x4.w + b4.w; o4.w = o4.w > 0.f ? o4.w : al * o4.w;
            *(float4*)&out[(size_t)row * 128 + k] = o4;
        }
        float4 wv4 = *(const float4*)&Wsc[(size_t)lrow * 128 + k];
        xs[lk + 0][lrow] = o4.x; xs[lk + 1][lrow] = o4.y;
        xs[lk + 2][lrow] = o4.z; xs[lk + 3][lrow] = o4.w;
        ws[lk + 0][lrow] = wv4.x; ws[lk + 1][lrow] = wv4.y;
        ws[lk + 2][lrow] = wv4.z; ws[lk + 3][lrow] = wv4.w;
        __syncthreads();
#pragma unroll
        for (int kk = 0; kk < 8; kk++) {
            float4 xa = *(const float4*)&xs[kk][tr * 8];
            float4 xb = *(const float4*)&xs[kk][tr * 8 + 4];
            ulonglong2 wlo = *(const ulonglong2*)&ws[kk][tc * 8];
            ulonglong2 whi = *(const ulonglong2*)&ws[kk][tc * 8 + 4];
            float xr[8] = {xa.x, xa.y, xa.z, xa.w, xb.x, xb.y, xb.z, xb.w};
#pragma unroll
            for (int i = 0; i < 8; i++) {
                u64 xd = p2(xr[i], xr[i]);
                fma2(acc[i][0], xd, wlo.x);
                fma2(acc[i][1], xd, wlo.y);
                fma2(acc[i][2], xd, whi.x);
                fma2(acc[i][3], xd, whi.y);
            }
        }
    }
#pragma unroll
    for (int i = 0; i < 8; i++) {
        int row = rb + tr * 8 + i;
        if (row < Nn) {
            ulonglong2 v0; v0.x = acc[i][0]; v0.y = acc[i][1];
            ulonglong2 v1; v1.x = acc[i][2]; v1.y = acc[i][3];
            *(ulonglong2*)&g_score[(size_t)row * 128 + tc * 8]     = v0;
            *(ulonglong2*)&g_score[(size_t)row * 128 + tc * 8 + 4] = v1;
        }
    }
}

// ---------------- K6: light readout — block/graph, warp/node -----------------
__global__ void k_rd2(const float* __restrict__ out, const int* __restrict__ batch,
                      const float* __restrict__ ww, const float* __restrict__ bw,
                      const float* __restrict__ bsc, float* dout) {
    __shared__ __align__(16) float red[8 * 128];
    __shared__ int bnds[2];
    int t = threadIdx.x, g = blockIdx.x;
    int w = t >> 5, l = t & 31;
    if (t < 2) {
        int tgt = g + t;
        int lo = 0, hi = Nn;
        while (lo < hi) {
            int mid = (lo + hi) >> 1;
            if (batch[mid] < tgt) lo = mid + 1; else hi = mid;
        }
        bnds[t] = lo;
    }
    __syncthreads();
    int beg = bnds[0], end = bnds[1];
    const float4 aw  = *(const float4*)&ww[4 * l];
    const float4 bs4 = *(const float4*)&bsc[4 * l];
    float bw0 = bw[0];
    float4 sum = make_float4(0.f, 0.f, 0.f, 0.f);
    float4 mx  = make_float4(-3.402823466e38f, -3.402823466e38f,
                             -3.402823466e38f, -3.402823466e38f);
    for (int n = beg + w; n < end; n += 8) {
        float4 o4 = *(const float4*)&out[(size_t)n * 128 + 4 * l];
        float4 s4 = *(const float4*)&g_score[(size_t)n * 128 + 4 * l];
        float v = o4.x * aw.x + o4.y * aw.y + o4.z * aw.z + o4.w * aw.w;
#pragma unroll
        for (int o = 16; o; o >>= 1) v += __shfl_xor_sync(0xffffffffu, v, o);
        float gw = 1.f / (1.f + __expf(-(v + bw0)));
        sum.x += gw * (s4.x + bs4.x);
        sum.y += gw * (s4.y + bs4.y);
        sum.z += gw * (s4.z + bs4.z);
        sum.w += gw * (s4.w + bs4.w);
        mx.x = fmaxf(mx.x, o4.x); mx.y = fmaxf(mx.y, o4.y);
        mx.z = fmaxf(mx.z, o4.z); mx.w = fmaxf(mx.w, o4.w);
    }
    *(float4*)&red[w * 128 + 4 * l] = sum;
    __syncthreads();
    if (w == 0) {
        float4 tot = make_float4(0.f, 0.f, 0.f, 0.f);
#pragma unroll
        for (int r = 0; r < 8; r++) {
            float4 v = *(const float4*)&red[r * 128 + 4 * l];
            tot.x += v.x; tot.y += v.y; tot.z += v.z; tot.w += v.w;
        }
        *(float4*)&dout[(size_t)Nn * 128 + g * 256 + 4 * l] = tot;
    }
    __syncthreads();
    *(float4*)&red[w * 128 + 4 * l] = mx;
    __syncthreads();
    if (w == 0) {
        float4 tot = make_float4(-3.402823466e38f, -3.402823466e38f,
                                 -3.402823466e38f, -3.402823466e38f);
#pragma unroll
        for (int r = 0; r < 8; r++) {
            float4 v = *(const float4*)&red[r * 128 + 4 * l];
            tot.x = fmaxf(tot.x, v.x); tot.y = fmaxf(tot.y, v.y);
            tot.z = fmaxf(tot.z, v.z); tot.w = fmaxf(tot.w, v.w);
        }
        *(float4*)&dout[(size_t)Nn * 128 + g * 256 + 128 + 4 * l] = tot;
    }
}

// ---------------- launch ------------------------------------------------------
extern "C" void kernel_launch(void* const* d_in, const int* in_sizes, int n_in,
                              void* d_out, int out_size) {
    const float* x     = (const float*)d_in[0];
    const int*   ei    = (const int*)d_in[1];
    const int*   batch = (const int*)d_in[2];
    const float* Wsrc  = (const float*)d_in[3];
    const float* Wdst  = (const float*)d_in[4];
    const float* attn  = (const float*)d_in[5];
    const float* bias  = (const float*)d_in[6];
    const float* prelu = (const float*)d_in[7];
    const float* ww    = (const float*)d_in[8];
    const float* bw    = (const float*)d_in[9];
    const float* Wsc   = (const float*)d_in[10];
    const float* bsc   = (const float*)d_in[11];
    float*       out   = (float*)d_out;

    k_projdeg<<<PROJ_BLKS + DEG_BLKS, 256>>>(x, Wsrc, Wdst, ei);   // 0
    k_scan<<<NBLK, 256>>>();                                       // 1
    k_scatter<<<(Ee + 511) / 512, 512>>>(ei);                      // 2
    k_edge<<<Nn / 8, 256>>>(attn);                                 // 3 <- ncu slot
    k_score<<<PROJ_BX, 256>>>(x, bias, prelu, Wsc, out);           // 4
    k_rd2<<<Gg, 256>>>(out, batch, ww, bw, bsc, out);              // 5
}

// round 10
// speedup vs baseline: 2.2370x; 1.0470x over previous
#include <cuda_runtime.h>
#include <cstdint>

#define Nn 50000
#define Ee 800000
#define Gg 512
#define NBLK 196          // ceil(Nn/256)
#define PROJ_BX 391       // ceil(Nn/128)

// ---------------- scratch ----------------------------------------------------
__device__ __align__(16) float  g_P[(size_t)Nn * 256];    // [N][256]: 0..127 src_p, 128..255 dst_p
__device__ __align__(16) float  g_acc[(size_t)Nn * 128];  // unnormalized aggregation
__device__ __align__(16) float  g_score[(size_t)Nn * 128];// out @ Wsc^T
__device__ __align__(16) float2 g_md[(size_t)Nn * 8];     // per (node,head): (max, denom)
__device__ __align__(16) int    g_deg[Nn];                // zero-init; self-cleaned
__device__ __align__(16) int    g_off[Nn + 1];
__device__ __align__(16) int    g_cur[Nn];
__device__ __align__(16) int    g_srcidx[Ee];
__device__ int      g_flag[NBLK];
__device__ int      g_done;
__device__ unsigned g_maxenc;

#define FLAG_A (1 << 24)
#define FLAG_P (1 << 25)
#define VALMSK 0xFFFFFF

// ---------------- f32x2 packed helpers ---------------------------------------
typedef unsigned long long u64;
__device__ __forceinline__ u64 p2(float lo, float hi) {
    u64 r;
    asm("mov.b64 %0, {%1, %2};" : "=l"(r) : "r"(__float_as_uint(lo)), "r"(__float_as_uint(hi)));
    return r;
}
__device__ __forceinline__ void fma2(u64& d, u64 a, u64 b) {
    asm("fma.rn.f32x2 %0, %1, %2, %3;" : "=l"(d) : "l"(a), "l"(b), "l"(d));
}
__device__ __forceinline__ unsigned encf(float f) {
    unsigned u = __float_as_uint(f);
    return (u & 0x80000000u) ? ~u : (u | 0x80000000u);
}
__device__ __forceinline__ float decf(unsigned e) {
    unsigned u = (e & 0x80000000u) ? (e & 0x7fffffffu) : ~e;
    return __uint_as_float(u);
}

// ---------------- K0: degree histogram ---------------------------------------
__global__ void k_deg(const int* __restrict__ ei) {
    int e = blockIdx.x * blockDim.x + threadIdx.x;
    if (e < Ee) atomicAdd(&g_deg[ei[Ee + e]], 1);
}

// ---------------- K1: decoupled-lookback exclusive scan ----------------------
__global__ void k_scan() {
    int b = blockIdx.x, t = threadIdx.x;
    int i = b * 256 + t;
    int v = (i < Nn) ? g_deg[i] : 0;
    if (i < Nn) g_deg[i] = 0;
    if (b == 0 && t == 1) g_maxenc = 0u;
    int lane = t & 31, w = t >> 5;
    int incl = v;
#pragma unroll
    for (int o = 1; o < 32; o <<= 1) {
        int u = __shfl_up_sync(0xffffffffu, incl, o);
        if (lane >= o) incl += u;
    }
    __shared__ int wsum[8];
    if (lane == 31) wsum[w] = incl;
    __syncthreads();
    if (w == 0) {
        int z = (lane < 8) ? wsum[lane] : 0;
#pragma unroll
        for (int o = 1; o < 8; o <<= 1) {
            int u = __shfl_up_sync(0xffffffffu, z, o);
            if (lane >= o) z += u;
        }
        if (lane < 8) wsum[lane] = z;
    }
    __syncthreads();
    incl += (w ? wsum[w - 1] : 0);
    __shared__ int blksum_s, prev_s;
    if (t == 255) blksum_s = incl;
    __syncthreads();
    int blksum = blksum_s;
    if (t == 0) {
        int prev = 0;
        if (b == 0) {
            atomicExch(&g_flag[0], FLAG_P | blksum);
        } else {
            atomicExch(&g_flag[b], FLAG_A | blksum);
            int j = b - 1;
            while (true) {
                int f;
                do { f = *(volatile int*)&g_flag[j]; } while (f == 0);
                prev += f & VALMSK;
                if (f & FLAG_P) break;
                j--;
            }
            atomicExch(&g_flag[b], FLAG_P | (prev + blksum));
        }
        prev_s = prev;
    }
    __syncthreads();
    int excl = prev_s + incl - v;
    if (i < Nn) { g_off[i] = excl; g_cur[i] = excl; }
    if (b == NBLK - 1 && t == 255) g_off[Nn] = prev_s + incl;
    if (t == 0) {
        int d = atomicAdd(&g_done, 1);
        if (d == NBLK - 1) {
            for (int j = 0; j < NBLK; j++) g_flag[j] = 0;
            g_done = 0;
        }
    }
}

// ---------------- K2: scatter edges into CSR slots ---------------------------
__global__ void k_scatter(const int* __restrict__ ei) {
    int e = blockIdx.x * blockDim.x + threadIdx.x;
    if (e < Ee) {
        int d = ei[Ee + e];
        int pos = atomicAdd(&g_cur[d], 1);
        g_srcidx[pos] = ei[e];
    }
}

// ---------------- K3: P = x @ W^T, 128x128 tile, double-buffered, FFMA2 ------
__global__ void k_proj(const float* __restrict__ x,
                       const float* __restrict__ Wsrc,
                       const float* __restrict__ Wdst) {
    __shared__ __align__(16) float xs[2][8][128];
    __shared__ __align__(16) float ws[2][8][128];
    int m = blockIdx.y;
    const float* W = m ? Wdst : Wsrc;
    int t  = threadIdx.x;
    int tr = t >> 4, tc = t & 15;
    int rb = blockIdx.x * 128;
    int lrow = t & 127, lk = (t >> 7) * 4;
    bool rowok = (rb + lrow) < Nn;
    const float* xrow = x + (size_t)(rb + lrow) * 128 + lk;
    const float* wrow = W + (size_t)lrow * 128 + lk;
    u64 acc[8][4];
#pragma unroll
    for (int i = 0; i < 8; i++)
#pragma unroll
        for (int j = 0; j < 4; j++) acc[i][j] = 0ull;

    // prologue: chunk 0
    {
        float4 xv4 = rowok ? *(const float4*)xrow : make_float4(0.f, 0.f, 0.f, 0.f);
        float4 wv4 = *(const float4*)wrow;
        xs[0][lk + 0][lrow] = xv4.x; xs[0][lk + 1][lrow] = xv4.y;
        xs[0][lk + 2][lrow] = xv4.z; xs[0][lk + 3][lrow] = xv4.w;
        ws[0][lk + 0][lrow] = wv4.x; ws[0][lk + 1][lrow] = wv4.y;
        ws[0][lk + 2][lrow] = wv4.z; ws[0][lk + 3][lrow] = wv4.w;
    }
    __syncthreads();
    int p = 0;
    for (int kc = 8; kc <= 128; kc += 8) {
        float4 nx, nw;
        bool more = kc < 128;
        if (more) {
            nx = rowok ? *(const float4*)(xrow + kc) : make_float4(0.f, 0.f, 0.f, 0.f);
            nw = *(const float4*)(wrow + kc);
        }
#pragma unroll
        for (int kk = 0; kk < 8; kk++) {
            float4 xa = *(const float4*)&xs[p][kk][tr * 8];
            float4 xb = *(const float4*)&xs[p][kk][tr * 8 + 4];
            ulonglong2 wlo = *(const ulonglong2*)&ws[p][kk][tc * 8];
            ulonglong2 whi = *(const ulonglong2*)&ws[p][kk][tc * 8 + 4];
            float xr[8] = {xa.x, xa.y, xa.z, xa.w, xb.x, xb.y, xb.z, xb.w};
#pragma unroll
            for (int i = 0; i < 8; i++) {
                u64 xd = p2(xr[i], xr[i]);
                fma2(acc[i][0], xd, wlo.x);
                fma2(acc[i][1], xd, wlo.y);
                fma2(acc[i][2], xd, whi.x);
                fma2(acc[i][3], xd, whi.y);
            }
        }
        if (more) {
            int q = p ^ 1;
            xs[q][lk + 0][lrow] = nx.x; xs[q][lk + 1][lrow] = nx.y;
            xs[q][lk + 2][lrow] = nx.z; xs[q][lk + 3][lrow] = nx.w;
            ws[q][lk + 0][lrow] = nw.x; ws[q][lk + 1][lrow] = nw.y;
            ws[q][lk + 2][lrow] = nw.z; ws[q][lk + 3][lrow] = nw.w;
            __syncthreads();
            p = q;
        }
    }
#pragma unroll
    for (int i = 0; i < 8; i++) {
        int row = rb + tr * 8 + i;
        if (row < Nn) {
            ulonglong2 v0; v0.x = acc[i][0]; v0.y = acc[i][1];
            ulonglong2 v1; v1.x = acc[i][2]; v1.y = acc[i][3];
            *(ulonglong2*)&g_P[(size_t)row * 256 + m * 128 + tc * 8]     = v0;
            *(ulonglong2*)&g_P[(size_t)row * 256 + m * 128 + tc * 8 + 4] = v1;
        }
    }
}

// ---------------- K4: fused logits + online-softmax aggregation --------------
__global__ void k_edge(const float* __restrict__ attn) {
    int wid = (blockIdx.x * blockDim.x + threadIdx.x) >> 5;
    int l = threadIdx.x & 31;
    if (wid >= Nn) return;
    int n = wid;
    const float4 dp = *(const float4*)&g_P[(size_t)n * 256 + 128 + 4 * l];
    float a0 = attn[4 * l], a1 = attn[4 * l + 1], a2 = attn[4 * l + 2], a3 = attn[4 * l + 3];
    float a0q = 0.2f * a0, a1q = 0.2f * a1, a2q = 0.2f * a2, a3q = 0.2f * a3;
    int beg = g_off[n], end = g_off[n + 1];
    float mh = -3.402823466e38f;
    float dh = 0.f;
    float4 acc = make_float4(0.f, 0.f, 0.f, 0.f);
    int i = beg;
    for (; i + 3 < end; i += 4) {
        int s0 = g_srcidx[i],     s1 = g_srcidx[i + 1];
        int s2 = g_srcidx[i + 2], s3 = g_srcidx[i + 3];
        float4 q0 = *(const float4*)&g_P[(size_t)s0 * 256 + 4 * l];
        float4 q1 = *(const float4*)&g_P[(size_t)s1 * 256 + 4 * l];
        float4 q2 = *(const float4*)&g_P[(size_t)s2 * 256 + 4 * l];
        float4 q3 = *(const float4*)&g_P[(size_t)s3 * 256 + 4 * l];
        float p0, p1, p2, p3;
        {
            float ex = q0.x + dp.x, ey = q0.y + dp.y, ez = q0.z + dp.z, ew = q0.w + dp.w;
            p0 = a0 * fmaxf(ex, 0.f) + a0q * fminf(ex, 0.f)
               + a1 * fmaxf(ey, 0.f) + a1q * fminf(ey, 0.f)
               + a2 * fmaxf(ez, 0.f) + a2q * fminf(ez, 0.f)
               + a3 * fmaxf(ew, 0.f) + a3q * fminf(ew, 0.f);
            ex = q1.x + dp.x; ey = q1.y + dp.y; ez = q1.z + dp.z; ew = q1.w + dp.w;
            p1 = a0 * fmaxf(ex, 0.f) + a0q * fminf(ex, 0.f)
               + a1 * fmaxf(ey, 0.f) + a1q * fminf(ey, 0.f)
               + a2 * fmaxf(ez, 0.f) + a2q * fminf(ez, 0.f)
               + a3 * fmaxf(ew, 0.f) + a3q * fminf(ew, 0.f);
            ex = q2.x + dp.x; ey = q2.y + dp.y; ez = q2.z + dp.z; ew = q2.w + dp.w;
            p2 = a0 * fmaxf(ex, 0.f) + a0q * fminf(ex, 0.f)
               + a1 * fmaxf(ey, 0.f) + a1q * fminf(ey, 0.f)
               + a2 * fmaxf(ez, 0.f) + a2q * fminf(ez, 0.f)
               + a3 * fmaxf(ew, 0.f) + a3q * fminf(ew, 0.f);
            ex = q3.x + dp.x; ey = q3.y + dp.y; ez = q3.z + dp.z; ew = q3.w + dp.w;
            p3 = a0 * fmaxf(ex, 0.f) + a0q * fminf(ex, 0.f)
               + a1 * fmaxf(ey, 0.f) + a1q * fminf(ey, 0.f)
               + a2 * fmaxf(ez, 0.f) + a2q * fminf(ez, 0.f)
               + a3 * fmaxf(ew, 0.f) + a3q * fminf(ew, 0.f);
        }
        p0 += __shfl_xor_sync(0xffffffffu, p0, 1);
        p1 += __shfl_xor_sync(0xffffffffu, p1, 1);
        p2 += __shfl_xor_sync(0xffffffffu, p2, 1);
        p3 += __shfl_xor_sync(0xffffffffu, p3, 1);
        p0 += __shfl_xor_sync(0xffffffffu, p0, 2);
        p1 += __shfl_xor_sync(0xffffffffu, p1, 2);
        p2 += __shfl_xor_sync(0xffffffffu, p2, 2);
        p3 += __shfl_xor_sync(0xffffffffu, p3, 2);
        float gm = fmaxf(fmaxf(p0, p1), fmaxf(p2, p3));
        float nm = fmaxf(mh, gm);
        float r  = __expf(mh - nm);
        float w0 = __expf(p0 - nm), w1 = __expf(p1 - nm);
        float w2 = __expf(p2 - nm), w3 = __expf(p3 - nm);
        dh = dh * r + (w0 + w1 + w2 + w3);
        acc.x = acc.x * r + w0 * q0.x + w1 * q1.x + w2 * q2.x + w3 * q3.x;
        acc.y = acc.y * r + w0 * q0.y + w1 * q1.y + w2 * q2.y + w3 * q3.y;
        acc.z = acc.z * r + w0 * q0.z + w1 * q1.z + w2 * q2.z + w3 * q3.z;
        acc.w = acc.w * r + w0 * q0.w + w1 * q1.w + w2 * q2.w + w3 * q3.w;
        mh = nm;
    }
    for (; i < end; i++) {
        int s0 = g_srcidx[i];
        float4 q0 = *(const float4*)&g_P[(size_t)s0 * 256 + 4 * l];
        float ex = q0.x + dp.x, ey = q0.y + dp.y, ez = q0.z + dp.z, ew = q0.w + dp.w;
        float p0 = a0 * fmaxf(ex, 0.f) + a0q * fminf(ex, 0.f)
                 + a1 * fmaxf(ey, 0.f) + a1q * fminf(ey, 0.f)
                 + a2 * fmaxf(ez, 0.f) + a2q * fminf(ez, 0.f)
                 + a3 * fmaxf(ew, 0.f) + a3q * fminf(ew, 0.f);
        p0 += __shfl_xor_sync(0xffffffffu, p0, 1);
        p0 += __shfl_xor_sync(0xffffffffu, p0, 2);
        float nm = fmaxf(mh, p0);
        float r  = __expf(mh - nm);
        float w0 = __expf(p0 - nm);
        dh = dh * r + w0;
        acc.x = acc.x * r + w0 * q0.x;
        acc.y = acc.y * r + w0 * q0.y;
        acc.z = acc.z * r + w0 * q0.z;
        acc.w = acc.w * r + w0 * q0.w;
        mh = nm;
    }
    *(float4*)&g_acc[(size_t)n * 128 + 4 * l] = acc;
    if ((l & 3) == 0) g_md[(size_t)n * 8 + (l >> 2)] = make_float2(mh, dh);
    if (beg < end) {
        float m = mh;
        for (int o = 16; o; o >>= 1) m = fmaxf(m, __shfl_xor_sync(0xffffffffu, m, o));
        if (l == 0) atomicMax(&g_maxenc, encf(m));
    }
}

// ---------------- K5: fused finalize + score GEMM (double-buffered) ----------
__global__ void k_score(const float* __restrict__ x, const float* __restrict__ bias,
                        const float* __restrict__ prelu, const float* __restrict__ Wsc,
                        float* out) {
    __shared__ __align__(16) float xs[2][8][128];
    __shared__ __align__(16) float ws[2][8][128];
    int t  = threadIdx.x;
    int tr = t >> 4, tc = t & 15;
    int rb = blockIdx.x * 128;
    int lrow = t & 127, lk = (t >> 7) * 4;
    bool rowok = (rb + lrow) < Nn;
    int row = rb + lrow;
    float al = prelu[0];
    float M = decf(g_maxenc);
    u64 acc[8][4];
#pragma unroll
    for (int i = 0; i < 8; i++)
#pragma unroll
        for (int j = 0; j < 4; j++) acc[i][j] = 0ull;

    auto loadout = [&](int k) -> float4 {
        float4 o4 = make_float4(0.f, 0.f, 0.f, 0.f);
        if (rowok) {
            float4 a4 = *(const float4*)&g_acc[(size_t)row * 128 + k];
            float2 md = g_md[(size_t)row * 8 + (k >> 4)];
            float s = __expf(md.x - M);
            float f = s / (s * md.y + 1e-16f);
            float4 x4 = *(const float4*)&x[(size_t)row * 128 + k];
            float4 b4 = *(const float4*)&bias[k];
            o4.x = a4.x * f + x4.x + b4.x; o4.x = o4.x > 0.f ? o4.x : al * o4.x;
            o4.y = a4.y * f + x4.y + b4.y; o4.y = o4.y > 0.f ? o4.y : al * o4.y;
            o4.z = a4.z * f + x4.z + b4.z; o4.z = o4.z > 0.f ? o4.z : al * o4.z;
            o4.w = a4.w * f + x4.w + b4.w; o4.w = o4.w > 0.f ? o4.w : al * o4.w;
            *(float4*)&out[(size_t)row * 128 + k] = o4;
        }
        return o4;
    };

    {
        float4 o4 = loadout(lk);
        float4 wv4 = *(const float4*)&Wsc[(size_t)lrow * 128 + lk];
        xs[0][lk + 0][lrow] = o4.x; xs[0][lk + 1][lrow] = o4.y;
        xs[0][lk + 2][lrow] = o4.z; xs[0][lk + 3][lrow] = o4.w;
        ws[0][lk + 0][lrow] = wv4.x; ws[0][lk + 1][lrow] = wv4.y;
        ws[0][lk + 2][lrow] = wv4.z; ws[0][lk + 3][lrow] = wv4.w;
    }
    __syncthreads();
    int p = 0;
    for (int kc = 8; kc <= 128; kc += 8) {
        float4 no4, nw4;
        bool more = kc < 128;
        if (more) {
            no4 = loadout(kc + lk);
            nw4 = *(const float4*)&Wsc[(size_t)lrow * 128 + kc + lk];
        }
#pragma unroll
        for (int kk = 0; kk < 8; kk++) {
            float4 xa = *(const float4*)&xs[p][kk][tr * 8];
            float4 xb = *(const float4*)&xs[p][kk][tr * 8 + 4];
            ulonglong2 wlo = *(const ulonglong2*)&ws[p][kk][tc * 8];
            ulonglong2 whi = *(const ulonglong2*)&ws[p][kk][tc * 8 + 4];
            float xr[8] = {xa.x, xa.y, xa.z, xa.w, xb.x, xb.y, xb.z, xb.w};
#pragma unroll
            for (int i = 0; i < 8; i++) {
                u64 xd = p2(xr[i], xr[i]);
                fma2(acc[i][0], xd, wlo.x);
                fma2(acc[i][1], xd, wlo.y);
                fma2(acc[i][2], xd, whi.x);
                fma2(acc[i][3], xd, whi.y);
            }
        }
        if (more) {
            int q = p ^ 1;
            xs[q][lk + 0][lrow] = no4.x; xs[q][lk + 1][lrow] = no4.y;
            xs[q][lk + 2][lrow] = no4.z; xs[q][lk + 3][lrow] = no4.w;
            ws[q][lk + 0][lrow] = nw4.x; ws[q][lk + 1][lrow] = nw4.y;
            ws[q][lk + 2][lrow] = nw4.z; ws[q][lk + 3][lrow] = nw4.w;
            __syncthreads();
            p = q;
        }
    }
#pragma unroll
    for (int i = 0; i < 8; i++) {
        int r2 = rb + tr * 8 + i;
        if (r2 < Nn) {
            ulonglong2 v0; v0.x = acc[i][0]; v0.y = acc[i][1];
            ulonglong2 v1; v1.x = acc[i][2]; v1.y = acc[i][3];
            *(ulonglong2*)&g_score[(size_t)r2 * 128 + tc * 8]     = v0;
            *(ulonglong2*)&g_score[(size_t)r2 * 128 + tc * 8 + 4] = v1;
        }
    }
}

// ---------------- K6: light readout — block/graph, warp/node -----------------
__global__ void k_rd2(const float* __restrict__ out, const int* __restrict__ batch,
                      const float* __restrict__ ww, const float* __restrict__ bw,
                      const float* __restrict__ bsc, float* dout) {
    __shared__ __align__(16) float red[8 * 128];
    __shared__ int bnds[2];
    int t = threadIdx.x, g = blockIdx.x;
    int w = t >> 5, l = t & 31;
    if (t < 2) {
        int tgt = g + t;
        int lo = 0, hi = Nn;
        while (lo < hi) {
            int mid = (lo + hi) >> 1;
            if (batch[mid] < tgt) lo = mid + 1; else hi = mid;
        }
        bnds[t] = lo;
    }
    __syncthreads();
    int beg = bnds[0], end = bnds[1];
    const float4 aw  = *(const float4*)&ww[4 * l];
    const float4 bs4 = *(const float4*)&bsc[4 * l];
    float bw0 = bw[0];
    float4 sum = make_float4(0.f, 0.f, 0.f, 0.f);
    float4 mx  = make_float4(-3.402823466e38f, -3.402823466e38f,
                             -3.402823466e38f, -3.402823466e38f);
    for (int n = beg + w; n < end; n += 8) {
        float4 o4 = *(const float4*)&out[(size_t)n * 128 + 4 * l];
        float4 s4 = *(const float4*)&g_score[(size_t)n * 128 + 4 * l];
        float v = o4.x * aw.x + o4.y * aw.y + o4.z * aw.z + o4.w * aw.w;
#pragma unroll
        for (int o = 16; o; o >>= 1) v += __shfl_xor_sync(0xffffffffu, v, o);
        float gw = 1.f / (1.f + __expf(-(v + bw0)));
        sum.x += gw * (s4.x + bs4.x);
        sum.y += gw * (s4.y + bs4.y);
        sum.z += gw * (s4.z + bs4.z);
        sum.w += gw * (s4.w + bs4.w);
        mx.x = fmaxf(mx.x, o4.x); mx.y = fmaxf(mx.y, o4.y);
        mx.z = fmaxf(mx.z, o4.z); mx.w = fmaxf(mx.w, o4.w);
    }
    *(float4*)&red[w * 128 + 4 * l] = sum;
    __syncthreads();
    if (w == 0) {
        float4 tot = make_float4(0.f, 0.f, 0.f, 0.f);
#pragma unroll
        for (int r = 0; r < 8; r++) {
            float4 v = *(const float4*)&red[r * 128 + 4 * l];
            tot.x += v.x; tot.y += v.y; tot.z += v.z; tot.w += v.w;
        }
        *(float4*)&dout[(size_t)Nn * 128 + g * 256 + 4 * l] = tot;
    }
    __syncthreads();
    *(float4*)&red[w * 128 + 4 * l] = mx;
    __syncthreads();
    if (w == 0) {
        float4 tot = make_float4(-3.402823466e38f, -3.402823466e38f,
                                 -3.402823466e38f, -3.402823466e38f);
#pragma unroll
        for (int r = 0; r < 8; r++) {
            float4 v = *(const float4*)&red[r * 128 + 4 * l];
            tot.x = fmaxf(tot.x, v.x); tot.y = fmaxf(tot.y, v.y);
            tot.z = fmaxf(tot.z, v.z); tot.w = fmaxf(tot.w, v.w);
        }
        *(float4*)&dout[(size_t)Nn * 128 + g * 256 + 128 + 4 * l] = tot;
    }
}

// ---------------- launch ------------------------------------------------------
extern "C" void kernel_launch(void* const* d_in, const int* in_sizes, int n_in,
                              void* d_out, int out_size) {
    const float* x     = (const float*)d_in[0];
    const int*   ei    = (const int*)d_in[1];
    const int*   batch = (const int*)d_in[2];
    const float* Wsrc  = (const float*)d_in[3];
    const float* Wdst  = (const float*)d_in[4];
    const float* attn  = (const float*)d_in[5];
    const float* bias  = (const float*)d_in[6];
    const float* prelu = (const float*)d_in[7];
    const float* ww    = (const float*)d_in[8];
    const float* bw    = (const float*)d_in[9];
    const float* Wsc   = (const float*)d_in[10];
    const float* bsc   = (const float*)d_in[11];
    float*       out   = (float*)d_out;

    k_deg<<<(Ee + 511) / 512, 512>>>(ei);                          // 0
    k_scan<<<NBLK, 256>>>();                                       // 1
    k_scatter<<<(Ee + 511) / 512, 512>>>(ei);                      // 2
    dim3 gp(PROJ_BX, 2);
    k_proj<<<gp, 256>>>(x, Wsrc, Wdst);                            // 3 <- ncu slot
    k_edge<<<Nn / 8, 256>>>(attn);                                 // 4
    k_score<<<PROJ_BX, 256>>>(x, bias, prelu, Wsc, out);           // 5
    k_rd2<<<Gg, 256>>>(out, batch, ww, bw, bsc, out);              // 6
}

// round 11
// speedup vs baseline: 2.4718x; 1.1050x over previous
#include <cuda_runtime.h>
#include <cstdint>

#define Nn 50000
#define Ee 800000
#define Gg 512
#define NBLK 196          // ceil(Nn/256)
#define PROJ_BX 391       // ceil(Nn/128)

// ---------------- scratch ----------------------------------------------------
__device__ __align__(16) float  g_P[(size_t)Nn * 256];    // [N][256]: 0..127 src_p, 128..255 dst_p
__device__ __align__(16) float  g_acc[(size_t)Nn * 128];  // unnormalized aggregation
__device__ __align__(16) float  g_score[(size_t)Nn * 128];// out @ Wsc^T
__device__ __align__(16) float2 g_md[(size_t)Nn * 8];     // per (node,head): (max, denom)
__device__ __align__(16) int    g_deg[Nn];                // zero-init; self-cleaned
__device__ __align__(16) int    g_off[Nn + 1];
__device__ __align__(16) int    g_cur[Nn];
__device__ __align__(16) int    g_srcidx[Ee];
__device__ int      g_flag[NBLK];
__device__ int      g_done;
__device__ unsigned g_maxenc;

#define FLAG_A (1 << 24)
#define FLAG_P (1 << 25)
#define VALMSK 0xFFFFFF

// ---------------- f32x2 packed helpers ---------------------------------------
typedef unsigned long long u64;
__device__ __forceinline__ u64 p2(float lo, float hi) {
    u64 r;
    asm("mov.b64 %0, {%1, %2};" : "=l"(r) : "r"(__float_as_uint(lo)), "r"(__float_as_uint(hi)));
    return r;
}
__device__ __forceinline__ void fma2(u64& d, u64 a, u64 b) {
    asm("fma.rn.f32x2 %0, %1, %2, %3;" : "=l"(d) : "l"(a), "l"(b), "l"(d));
}
__device__ __forceinline__ unsigned encf(float f) {
    unsigned u = __float_as_uint(f);
    return (u & 0x80000000u) ? ~u : (u | 0x80000000u);
}
__device__ __forceinline__ float decf(unsigned e) {
    unsigned u = (e & 0x80000000u) ? (e & 0x7fffffffu) : ~e;
    return __uint_as_float(u);
}

// ---------------- K0: degree histogram ---------------------------------------
__global__ void k_deg(const int* __restrict__ ei) {
    int e = blockIdx.x * blockDim.x + threadIdx.x;
    if (e < Ee) atomicAdd(&g_deg[ei[Ee + e]], 1);
}

// ---------------- K1: decoupled-lookback exclusive scan ----------------------
__global__ void k_scan() {
    int b = blockIdx.x, t = threadIdx.x;
    int i = b * 256 + t;
    int v = (i < Nn) ? g_deg[i] : 0;
    if (i < Nn) g_deg[i] = 0;
    if (b == 0 && t == 1) g_maxenc = 0u;
    int lane = t & 31, w = t >> 5;
    int incl = v;
#pragma unroll
    for (int o = 1; o < 32; o <<= 1) {
        int u = __shfl_up_sync(0xffffffffu, incl, o);
        if (lane >= o) incl += u;
    }
    __shared__ int wsum[8];
    if (lane == 31) wsum[w] = incl;
    __syncthreads();
    if (w == 0) {
        int z = (lane < 8) ? wsum[lane] : 0;
#pragma unroll
        for (int o = 1; o < 8; o <<= 1) {
            int u = __shfl_up_sync(0xffffffffu, z, o);
            if (lane >= o) z += u;
        }
        if (lane < 8) wsum[lane] = z;
    }
    __syncthreads();
    incl += (w ? wsum[w - 1] : 0);
    __shared__ int blksum_s, prev_s;
    if (t == 255) blksum_s = incl;
    __syncthreads();
    int blksum = blksum_s;
    if (t == 0) {
        int prev = 0;
        if (b == 0) {
            atomicExch(&g_flag[0], FLAG_P | blksum);
        } else {
            atomicExch(&g_flag[b], FLAG_A | blksum);
            int j = b - 1;
            while (true) {
                int f;
                do { f = *(volatile int*)&g_flag[j]; } while (f == 0);
                prev += f & VALMSK;
                if (f & FLAG_P) break;
                j--;
            }
            atomicExch(&g_flag[b], FLAG_P | (prev + blksum));
        }
        prev_s = prev;
    }
    __syncthreads();
    int excl = prev_s + incl - v;
    if (i < Nn) { g_off[i] = excl; g_cur[i] = excl; }
    if (b == NBLK - 1 && t == 255) g_off[Nn] = prev_s + incl;
    if (t == 0) {
        int d = atomicAdd(&g_done, 1);
        if (d == NBLK - 1) {
            for (int j = 0; j < NBLK; j++) g_flag[j] = 0;
            g_done = 0;
        }
    }
}

// ---------------- K2: scatter edges into CSR slots ---------------------------
__global__ void k_scatter(const int* __restrict__ ei) {
    int e = blockIdx.x * blockDim.x + threadIdx.x;
    if (e < Ee) {
        int d = ei[Ee + e];
        int pos = atomicAdd(&g_cur[d], 1);
        g_srcidx[pos] = ei[e];
    }
}

// ---------------- K3: P = x @ W^T, 128x128 tile, conflict-free split tile ----
// Thread owns rows {tr*4..+3, 64+tr*4..+3} x cols {tc*4..+3, 64+tc*4..+3}.
// Quarter-warp LDS reads are 128B contiguous -> conflict-free.
__global__ void k_proj(const float* __restrict__ x,
                       const float* __restrict__ Wsrc,
                       const float* __restrict__ Wdst) {
    __shared__ __align__(16) float xs[2][8][128];
    __shared__ __align__(16) float ws[2][8][128];
    int m = blockIdx.y;
    const float* W = m ? Wdst : Wsrc;
    int t  = threadIdx.x;
    int tr = t >> 4, tc = t & 15;
    int rb = blockIdx.x * 128;
    int lrow = t & 127, lk = (t >> 7) * 4;
    bool rowok = (rb + lrow) < Nn;
    const float* xrow = x + (size_t)(rb + lrow) * 128 + lk;
    const float* wrow = W + (size_t)lrow * 128 + lk;
    u64 acc[8][4];
#pragma unroll
    for (int i = 0; i < 8; i++)
#pragma unroll
        for (int j = 0; j < 4; j++) acc[i][j] = 0ull;

    {
        float4 xv4 = rowok ? *(const float4*)xrow : make_float4(0.f, 0.f, 0.f, 0.f);
        float4 wv4 = *(const float4*)wrow;
        xs[0][lk + 0][lrow] = xv4.x; xs[0][lk + 1][lrow] = xv4.y;
        xs[0][lk + 2][lrow] = xv4.z; xs[0][lk + 3][lrow] = xv4.w;
        ws[0][lk + 0][lrow] = wv4.x; ws[0][lk + 1][lrow] = wv4.y;
        ws[0][lk + 2][lrow] = wv4.z; ws[0][lk + 3][lrow] = wv4.w;
    }
    __syncthreads();
    int p = 0;
    for (int kc = 8; kc <= 128; kc += 8) {
        float4 nx, nw;
        bool more = kc < 128;
        if (more) {
            nx = rowok ? *(const float4*)(xrow + kc) : make_float4(0.f, 0.f, 0.f, 0.f);
            nw = *(const float4*)(wrow + kc);
        }
#pragma unroll
        for (int kk = 0; kk < 8; kk++) {
            float4 xa = *(const float4*)&xs[p][kk][tr * 4];
            float4 xb = *(const float4*)&xs[p][kk][64 + tr * 4];
            ulonglong2 wlo = *(const ulonglong2*)&ws[p][kk][tc * 4];
            ulonglong2 whi = *(const ulonglong2*)&ws[p][kk][64 + tc * 4];
            float xr0[4] = {xa.x, xa.y, xa.z, xa.w};
            float xr1[4] = {xb.x, xb.y, xb.z, xb.w};
#pragma unroll
            for (int i = 0; i < 4; i++) {
                u64 xd = p2(xr0[i], xr0[i]);
                fma2(acc[i][0], xd, wlo.x);
                fma2(acc[i][1], xd, wlo.y);
                fma2(acc[i][2], xd, whi.x);
                fma2(acc[i][3], xd, whi.y);
            }
#pragma unroll
            for (int i = 0; i < 4; i++) {
                u64 xd = p2(xr1[i], xr1[i]);
                fma2(acc[4 + i][0], xd, wlo.x);
                fma2(acc[4 + i][1], xd, wlo.y);
                fma2(acc[4 + i][2], xd, whi.x);
                fma2(acc[4 + i][3], xd, whi.y);
            }
        }
        if (more) {
            int q = p ^ 1;
            xs[q][lk + 0][lrow] = nx.x; xs[q][lk + 1][lrow] = nx.y;
            xs[q][lk + 2][lrow] = nx.z; xs[q][lk + 3][lrow] = nx.w;
            ws[q][lk + 0][lrow] = nw.x; ws[q][lk + 1][lrow] = nw.y;
            ws[q][lk + 2][lrow] = nw.z; ws[q][lk + 3][lrow] = nw.w;
            __syncthreads();
            p = q;
        }
    }
#pragma unroll
    for (int i = 0; i < 8; i++) {
        int row = rb + (i < 4 ? tr * 4 + i : 64 + tr * 4 + (i - 4));
        if (row < Nn) {
            ulonglong2 v0; v0.x = acc[i][0]; v0.y = acc[i][1];
            ulonglong2 v1; v1.x = acc[i][2]; v1.y = acc[i][3];
            *(ulonglong2*)&g_P[(size_t)row * 256 + m * 128 + tc * 4]      = v0;
            *(ulonglong2*)&g_P[(size_t)row * 256 + m * 128 + 64 + tc * 4] = v1;
        }
    }
}

// ---------------- K4: fused logits + online-softmax aggregation --------------
__global__ void k_edge(const float* __restrict__ attn) {
    int wid = (blockIdx.x * blockDim.x + threadIdx.x) >> 5;
    int l = threadIdx.x & 31;
    if (wid >= Nn) return;
    int n = wid;
    const float4 dp = *(const float4*)&g_P[(size_t)n * 256 + 128 + 4 * l];
    float a0 = attn[4 * l], a1 = attn[4 * l + 1], a2 = attn[4 * l + 2], a3 = attn[4 * l + 3];
    float a0q = 0.2f * a0, a1q = 0.2f * a1, a2q = 0.2f * a2, a3q = 0.2f * a3;
    int beg = g_off[n], end = g_off[n + 1];
    float mh = -3.402823466e38f;
    float dh = 0.f;
    float4 acc = make_float4(0.f, 0.f, 0.f, 0.f);
    int i = beg;
    for (; i + 3 < end; i += 4) {
        int s0 = g_srcidx[i],     s1 = g_srcidx[i + 1];
        int s2 = g_srcidx[i + 2], s3 = g_srcidx[i + 3];
        float4 q0 = *(const float4*)&g_P[(size_t)s0 * 256 + 4 * l];
        float4 q1 = *(const float4*)&g_P[(size_t)s1 * 256 + 4 * l];
        float4 q2 = *(const float4*)&g_P[(size_t)s2 * 256 + 4 * l];
        float4 q3 = *(const float4*)&g_P[(size_t)s3 * 256 + 4 * l];
        float p0, p1, p2, p3;
        {
            float ex = q0.x + dp.x, ey = q0.y + dp.y, ez = q0.z + dp.z, ew = q0.w + dp.w;
            p0 = a0 * fmaxf(ex, 0.f) + a0q * fminf(ex, 0.f)
               + a1 * fmaxf(ey, 0.f) + a1q * fminf(ey, 0.f)
               + a2 * fmaxf(ez, 0.f) + a2q * fminf(ez, 0.f)
               + a3 * fmaxf(ew, 0.f) + a3q * fminf(ew, 0.f);
            ex = q1.x + dp.x; ey = q1.y + dp.y; ez = q1.z + dp.z; ew = q1.w + dp.w;
            p1 = a0 * fmaxf(ex, 0.f) + a0q * fminf(ex, 0.f)
               + a1 * fmaxf(ey, 0.f) + a1q * fminf(ey, 0.f)
               + a2 * fmaxf(ez, 0.f) + a2q * fminf(ez, 0.f)
               + a3 * fmaxf(ew, 0.f) + a3q * fminf(ew, 0.f);
            ex = q2.x + dp.x; ey = q2.y + dp.y; ez = q2.z + dp.z; ew = q2.w + dp.w;
            p2 = a0 * fmaxf(ex, 0.f) + a0q * fminf(ex, 0.f)
               + a1 * fmaxf(ey, 0.f) + a1q * fminf(ey, 0.f)
               + a2 * fmaxf(ez, 0.f) + a2q * fminf(ez, 0.f)
               + a3 * fmaxf(ew, 0.f) + a3q * fminf(ew, 0.f);
            ex = q3.x + dp.x; ey = q3.y + dp.y; ez = q3.z + dp.z; ew = q3.w + dp.w;
            p3 = a0 * fmaxf(ex, 0.f) + a0q * fminf(ex, 0.f)
               + a1 * fmaxf(ey, 0.f) + a1q * fminf(ey, 0.f)
               + a2 * fmaxf(ez, 0.f) + a2q * fminf(ez, 0.f)
               + a3 * fmaxf(ew, 0.f) + a3q * fminf(ew, 0.f);
        }
        p0 += __shfl_xor_sync(0xffffffffu, p0, 1);
        p1 += __shfl_xor_sync(0xffffffffu, p1, 1);
        p2 += __shfl_xor_sync(0xffffffffu, p2, 1);
        p3 += __shfl_xor_sync(0xffffffffu, p3, 1);
        p0 += __shfl_xor_sync(0xffffffffu, p0, 2);
        p1 += __shfl_xor_sync(0xffffffffu, p1, 2);
        p2 += __shfl_xor_sync(0xffffffffu, p2, 2);
        p3 += __shfl_xor_sync(0xffffffffu, p3, 2);
        float gm = fmaxf(fmaxf(p0, p1), fmaxf(p2, p3));
        float nm = fmaxf(mh, gm);
        float r  = __expf(mh - nm);
        float w0 = __expf(p0 - nm), w1 = __expf(p1 - nm);
        float w2 = __expf(p2 - nm), w3 = __expf(p3 - nm);
        dh = dh * r + (w0 + w1 + w2 + w3);
        acc.x = acc.x * r + w0 * q0.x + w1 * q1.x + w2 * q2.x + w3 * q3.x;
        acc.y = acc.y * r + w0 * q0.y + w1 * q1.y + w2 * q2.y + w3 * q3.y;
        acc.z = acc.z * r + w0 * q0.z + w1 * q1.z + w2 * q2.z + w3 * q3.z;
        acc.w = acc.w * r + w0 * q0.w + w1 * q1.w + w2 * q2.w + w3 * q3.w;
        mh = nm;
    }
    for (; i < end; i++) {
        int s0 = g_srcidx[i];
        float4 q0 = *(const float4*)&g_P[(size_t)s0 * 256 + 4 * l];
        float ex = q0.x + dp.x, ey = q0.y + dp.y, ez = q0.z + dp.z, ew = q0.w + dp.w;
        float p0 = a0 * fmaxf(ex, 0.f) + a0q * fminf(ex, 0.f)
                 + a1 * fmaxf(ey, 0.f) + a1q * fminf(ey, 0.f)
                 + a2 * fmaxf(ez, 0.f) + a2q * fminf(ez, 0.f)
                 + a3 * fmaxf(ew, 0.f) + a3q * fminf(ew, 0.f);
        p0 += __shfl_xor_sync(0xffffffffu, p0, 1);
        p0 += __shfl_xor_sync(0xffffffffu, p0, 2);
        float nm = fmaxf(mh, p0);
        float r  = __expf(mh - nm);
        float w0 = __expf(p0 - nm);
        dh = dh * r + w0;
        acc.x = acc.x * r + w0 * q0.x;
        acc.y = acc.y * r + w0 * q0.y;
        acc.z = acc.z * r + w0 * q0.z;
        acc.w = acc.w * r + w0 * q0.w;
        mh = nm;
    }
    *(float4*)&g_acc[(size_t)n * 128 + 4 * l] = acc;
    if ((l & 3) == 0) g_md[(size_t)n * 8 + (l >> 2)] = make_float2(mh, dh);
    if (beg < end) {
        float m = mh;
        for (int o = 16; o; o >>= 1) m = fmaxf(m, __shfl_xor_sync(0xffffffffu, m, o));
        if (l == 0) atomicMax(&g_maxenc, encf(m));
    }
}

// ---------------- K5: fused finalize + score GEMM (conflict-free split) ------
__global__ void k_score(const float* __restrict__ x, const float* __restrict__ bias,
                        const float* __restrict__ prelu, const float* __restrict__ Wsc,
                        float* out) {
    __shared__ __align__(16) float xs[2][8][128];
    __shared__ __align__(16) float ws[2][8][128];
    int t  = threadIdx.x;
    int tr = t >> 4, tc = t & 15;
    int rb = blockIdx.x * 128;
    int lrow = t & 127, lk = (t >> 7) * 4;
    bool rowok = (rb + lrow) < Nn;
    int row = rb + lrow;
    float al = prelu[0];
    float M = decf(g_maxenc);
    u64 acc[8][4];
#pragma unroll
    for (int i = 0; i < 8; i++)
#pragma unroll
        for (int j = 0; j < 4; j++) acc[i][j] = 0ull;

    auto loadout = [&](int k) -> float4 {
        float4 o4 = make_float4(0.f, 0.f, 0.f, 0.f);
        if (rowok) {
            float4 a4 = *(const float4*)&g_acc[(size_t)row * 128 + k];
            float2 md = g_md[(size_t)row * 8 + (k >> 4)];
            float s = __expf(md.x - M);
            float f = s / (s * md.y + 1e-16f);
            float4 x4 = *(const float4*)&x[(size_t)row * 128 + k];
            float4 b4 = *(const float4*)&bias[k];
            o4.x = a4.x * f + x4.x + b4.x; o4.x = o4.x > 0.f ? o4.x : al * o4.x;
            o4.y = a4.y * f + x4.y + b4.y; o4.y = o4.y > 0.f ? o4.y : al * o4.y;
            o4.z = a4.z * f + x4.z + b4.z; o4.z = o4.z > 0.f ? o4.z : al * o4.z;
            o4.w = a4.w * f + x4.w + b4.w; o4.w = o4.w > 0.f ? o4.w : al * o4.w;
            *(float4*)&out[(size_t)row * 128 + k] = o4;
        }
        return o4;
    };

    {
        float4 o4 = loadout(lk);
        float4 wv4 = *(const float4*)&Wsc[(size_t)lrow * 128 + lk];
        xs[0][lk + 0][lrow] = o4.x; xs[0][lk + 1][lrow] = o4.y;
        xs[0][lk + 2][lrow] = o4.z; xs[0][lk + 3][lrow] = o4.w;
        ws[0][lk + 0][lrow] = wv4.x; ws[0][lk + 1][lrow] = wv4.y;
        ws[0][lk + 2][lrow] = wv4.z; ws[0][lk + 3][lrow] = wv4.w;
    }
    __syncthreads();
    int p = 0;
    for (int kc = 8; kc <= 128; kc += 8) {
        float4 no4, nw4;
        bool more = kc < 128;
        if (more) {
            no4 = loadout(kc + lk);
            nw4 = *(const float4*)&Wsc[(size_t)lrow * 128 + kc + lk];
        }
#pragma unroll
        for (int kk = 0; kk < 8; kk++) {
            float4 xa = *(const float4*)&xs[p][kk][tr * 4];
            float4 xb = *(const float4*)&xs[p][kk][64 + tr * 4];
            ulonglong2 wlo = *(const ulonglong2*)&ws[p][kk][tc * 4];
            ulonglong2 whi = *(const ulonglong2*)&ws[p][kk][64 + tc * 4];
            float xr0[4] = {xa.x, xa.y, xa.z, xa.w};
            float xr1[4] = {xb.x, xb.y, xb.z, xb.w};
#pragma unroll
            for (int i = 0; i < 4; i++) {
                u64 xd = p2(xr0[i], xr0[i]);
                fma2(acc[i][0], xd, wlo.x);
                fma2(acc[i][1], xd, wlo.y);
                fma2(acc[i][2], xd, whi.x);
                fma2(acc[i][3], xd, whi.y);
            }
#pragma unroll
            for (int i = 0; i < 4; i++) {
                u64 xd = p2(xr1[i], xr1[i]);
                fma2(acc[4 + i][0], xd, wlo.x);
                fma2(acc[4 + i][1], xd, wlo.y);
                fma2(acc[4 + i][2], xd, whi.x);
                fma2(acc[4 + i][3], xd, whi.y);
            }
        }
        if (more) {
            int q = p ^ 1;
            xs[q][lk + 0][lrow] = no4.x; xs[q][lk + 1][lrow] = no4.y;
            xs[q][lk + 2][lrow] = no4.z; xs[q][lk + 3][lrow] = no4.w;
            ws[q][lk + 0][lrow] = nw4.x; ws[q][lk + 1][lrow] = nw4.y;
            ws[q][lk + 2][lrow] = nw4.z; ws[q][lk + 3][lrow] = nw4.w;
            __syncthreads();
            p = q;
        }
    }
#pragma unroll
    for (int i = 0; i < 8; i++) {
        int r2 = rb + (i < 4 ? tr * 4 + i : 64 + tr * 4 + (i - 4));
        if (r2 < Nn) {
            ulonglong2 v0; v0.x = acc[i][0]; v0.y = acc[i][1];
            ulonglong2 v1; v1.x = acc[i][2]; v1.y = acc[i][3];
            *(ulonglong2*)&g_score[(size_t)r2 * 128 + tc * 4]      = v0;
            *(ulonglong2*)&g_score[(size_t)r2 * 128 + 64 + tc * 4] = v1;
        }
    }
}

// ---------------- K6: light readout — block/graph, warp/node -----------------
__global__ void k_rd2(const float* __restrict__ out, const int* __restrict__ batch,
                      const float* __restrict__ ww, const float* __restrict__ bw,
                      const float* __restrict__ bsc, float* dout) {
    __shared__ __align__(16) float red[8 * 128];
    __shared__ int bnds[2];
    int t = threadIdx.x, g = blockIdx.x;
    int w = t >> 5, l = t & 31;
    if (t < 2) {
        int tgt = g + t;
        int lo = 0, hi = Nn;
        while (lo < hi) {
            int mid = (lo + hi) >> 1;
            if (batch[mid] < tgt) lo = mid + 1; else hi = mid;
        }
        bnds[t] = lo;
    }
    __syncthreads();
    int beg = bnds[0], end = bnds[1];
    const float4 aw  = *(const float4*)&ww[4 * l];
    const float4 bs4 = *(const float4*)&bsc[4 * l];
    float bw0 = bw[0];
    float4 sum = make_float4(0.f, 0.f, 0.f, 0.f);
    float4 mx  = make_float4(-3.402823466e38f, -3.402823466e38f,
                             -3.402823466e38f, -3.402823466e38f);
    for (int n = beg + w; n < end; n += 8) {
        float4 o4 = *(const float4*)&out[(size_t)n * 128 + 4 * l];
        float4 s4 = *(const float4*)&g_score[(size_t)n * 128 + 4 * l];
        float v = o4.x * aw.x + o4.y * aw.y + o4.z * aw.z + o4.w * aw.w;
#pragma unroll
        for (int o = 16; o; o >>= 1) v += __shfl_xor_sync(0xffffffffu, v, o);
        float gw = 1.f / (1.f + __expf(-(v + bw0)));
        sum.x += gw * (s4.x + bs4.x);
        sum.y += gw * (s4.y + bs4.y);
        sum.z += gw * (s4.z + bs4.z);
        sum.w += gw * (s4.w + bs4.w);
        mx.x = fmaxf(mx.x, o4.x); mx.y = fmaxf(mx.y, o4.y);
        mx.z = fmaxf(mx.z, o4.z); mx.w = fmaxf(mx.w, o4.w);
    }
    *(float4*)&red[w * 128 + 4 * l] = sum;
    __syncthreads();
    if (w == 0) {
        float4 tot = make_float4(0.f, 0.f, 0.f, 0.f);
#pragma unroll
        for (int r = 0; r < 8; r++) {
            float4 v = *(const float4*)&red[r * 128 + 4 * l];
            tot.x += v.x; tot.y += v.y; tot.z += v.z; tot.w += v.w;
        }
        *(float4*)&dout[(size_t)Nn * 128 + g * 256 + 4 * l] = tot;
    }
    __syncthreads();
    *(float4*)&red[w * 128 + 4 * l] = mx;
    __syncthreads();
    if (w == 0) {
        float4 tot = make_float4(-3.402823466e38f, -3.402823466e38f,
                                 -3.402823466e38f, -3.402823466e38f);
#pragma unroll
        for (int r = 0; r < 8; r++) {
            float4 v = *(const float4*)&red[r * 128 + 4 * l];
            tot.x = fmaxf(tot.x, v.x); tot.y = fmaxf(tot.y, v.y);
            tot.z = fmaxf(tot.z, v.z); tot.w = fmaxf(tot.w, v.w);
        }
        *(float4*)&dout[(size_t)Nn * 128 + g * 256 + 128 + 4 * l] = tot;
    }
}

// ---------------- launch ------------------------------------------------------
extern "C" void kernel_launch(void* const* d_in, const int* in_sizes, int n_in,
                              void* d_out, int out_size) {
    const float* x     = (const float*)d_in[0];
    const int*   ei    = (const int*)d_in[1];
    const int*   batch = (const int*)d_in[2];
    const float* Wsrc  = (const float*)d_in[3];
    const float* Wdst  = (const float*)d_in[4];
    const float* attn  = (const float*)d_in[5];
    const float* bias  = (const float*)d_in[6];
    const float* prelu = (const float*)d_in[7];
    const float* ww    = (const float*)d_in[8];
    const float* bw    = (const float*)d_in[9];
    const float* Wsc   = (const float*)d_in[10];
    const float* bsc   = (const float*)d_in[11];
    float*       out   = (float*)d_out;

    k_deg<<<(Ee + 511) / 512, 512>>>(ei);                          // 0
    k_scan<<<NBLK, 256>>>();                                       // 1
    k_scatter<<<(Ee + 511) / 512, 512>>>(ei);                      // 2
    dim3 gp(PROJ_BX, 2);
    k_proj<<<gp, 256>>>(x, Wsrc, Wdst);                            // 3 <- ncu slot
    k_edge<<<Nn / 8, 256>>>(attn);                                 // 4
    k_score<<<PROJ_BX, 256>>>(x, bias, prelu, Wsc, out);           // 5
    k_rd2<<<Gg, 256>>>(out, batch, ww, bw, bsc, out);              // 6
}

// round 12
// speedup vs baseline: 2.5975x; 1.0509x over previous
#include <cuda_runtime.h>
#include <cstdint>

#define Nn 50000
#define Ee 800000
#define Gg 512
#define NBLK 196          // ceil(Nn/256)
#define PROJ_BX 391       // ceil(Nn/128)

// ---------------- scratch ----------------------------------------------------
__device__ __align__(16) float  g_P[(size_t)Nn * 256];    // [N][256]: 0..127 src_p, 128..255 dst_p
__device__ __align__(16) float  g_acc[(size_t)Nn * 128];  // unnormalized aggregation
__device__ __align__(16) float  g_score[(size_t)Nn * 128];// out @ Wsc^T
__device__ __align__(16) float2 g_md[(size_t)Nn * 8];     // per (node,head): (max, denom)
__device__ __align__(16) int    g_deg[Nn];                // zero-init; self-cleaned
__device__ __align__(16) int    g_off[Nn + 1];
__device__ __align__(16) int    g_cur[Nn];
__device__ __align__(16) int    g_srcidx[Ee];
__device__ int      g_flag[NBLK];
__device__ int      g_done;
__device__ unsigned g_maxenc;

#define FLAG_A (1 << 24)
#define FLAG_P (1 << 25)
#define VALMSK 0xFFFFFF

// ---------------- stream/event handles (created at static init, pre-baseline) -
struct SideStream {
    cudaStream_t s = nullptr;
    cudaEvent_t  e0 = nullptr, e1 = nullptr;
    SideStream() {
        cudaStreamCreateWithFlags(&s, cudaStreamNonBlocking);
        cudaEventCreateWithFlags(&e0, cudaEventDisableTiming);
        cudaEventCreateWithFlags(&e1, cudaEventDisableTiming);
    }
};
static SideStream g_ss;

// ---------------- f32x2 packed helpers ---------------------------------------
typedef unsigned long long u64;
__device__ __forceinline__ u64 p2(float lo, float hi) {
    u64 r;
    asm("mov.b64 %0, {%1, %2};" : "=l"(r) : "r"(__float_as_uint(lo)), "r"(__float_as_uint(hi)));
    return r;
}
__device__ __forceinline__ void fma2(u64& d, u64 a, u64 b) {
    asm("fma.rn.f32x2 %0, %1, %2, %3;" : "=l"(d) : "l"(a), "l"(b), "l"(d));
}
__device__ __forceinline__ unsigned encf(float f) {
    unsigned u = __float_as_uint(f);
    return (u & 0x80000000u) ? ~u : (u | 0x80000000u);
}
__device__ __forceinline__ float decf(unsigned e) {
    unsigned u = (e & 0x80000000u) ? (e & 0x7fffffffu) : ~e;
    return __uint_as_float(u);
}

// ---------------- K0: degree histogram ---------------------------------------
__global__ void k_deg(const int* __restrict__ ei) {
    int e = blockIdx.x * blockDim.x + threadIdx.x;
    if (e < Ee) atomicAdd(&g_deg[ei[Ee + e]], 1);
}

// ---------------- K1: decoupled-lookback exclusive scan ----------------------
__global__ void k_scan() {
    int b = blockIdx.x, t = threadIdx.x;
    int i = b * 256 + t;
    int v = (i < Nn) ? g_deg[i] : 0;
    if (i < Nn) g_deg[i] = 0;
    if (b == 0 && t == 1) g_maxenc = 0u;
    int lane = t & 31, w = t >> 5;
    int incl = v;
#pragma unroll
    for (int o = 1; o < 32; o <<= 1) {
        int u = __shfl_up_sync(0xffffffffu, incl, o);
        if (lane >= o) incl += u;
    }
    __shared__ int wsum[8];
    if (lane == 31) wsum[w] = incl;
    __syncthreads();
    if (w == 0) {
        int z = (lane < 8) ? wsum[lane] : 0;
#pragma unroll
        for (int o = 1; o < 8; o <<= 1) {
            int u = __shfl_up_sync(0xffffffffu, z, o);
            if (lane >= o) z += u;
        }
        if (lane < 8) wsum[lane] = z;
    }
    __syncthreads();
    incl += (w ? wsum[w - 1] : 0);
    __shared__ int blksum_s, prev_s;
    if (t == 255) blksum_s = incl;
    __syncthreads();
    int blksum = blksum_s;
    if (t == 0) {
        int prev = 0;
        if (b == 0) {
            atomicExch(&g_flag[0], FLAG_P | blksum);
        } else {
            atomicExch(&g_flag[b], FLAG_A | blksum);
            int j = b - 1;
            while (true) {
                int f;
                do { f = *(volatile int*)&g_flag[j]; } while (f == 0);
                prev += f & VALMSK;
                if (f & FLAG_P) break;
                j--;
            }
            atomicExch(&g_flag[b], FLAG_P | (prev + blksum));
        }
        prev_s = prev;
    }
    __syncthreads();
    int excl = prev_s + incl - v;
    if (i < Nn) { g_off[i] = excl; g_cur[i] = excl; }
    if (b == NBLK - 1 && t == 255) g_off[Nn] = prev_s + incl;
    if (t == 0) {
        int d = atomicAdd(&g_done, 1);
        if (d == NBLK - 1) {
            for (int j = 0; j < NBLK; j++) g_flag[j] = 0;
            g_done = 0;
        }
    }
}

// ---------------- K2: scatter edges into CSR slots ---------------------------
__global__ void k_scatter(const int* __restrict__ ei) {
    int e = blockIdx.x * blockDim.x + threadIdx.x;
    if (e < Ee) {
        int d = ei[Ee + e];
        int pos = atomicAdd(&g_cur[d], 1);
        g_srcidx[pos] = ei[e];
    }
}

// ---------------- K3: P = x @ W^T, 128x128 tile, conflict-free split tile ----
__global__ void k_proj(const float* __restrict__ x,
                       const float* __restrict__ Wsrc,
                       const float* __restrict__ Wdst) {
    __shared__ __align__(16) float xs[2][8][128];
    __shared__ __align__(16) float ws[2][8][128];
    int m = blockIdx.y;
    const float* W = m ? Wdst : Wsrc;
    int t  = threadIdx.x;
    int tr = t >> 4, tc = t & 15;
    int rb = blockIdx.x * 128;
    int lrow = t & 127, lk = (t >> 7) * 4;
    bool rowok = (rb + lrow) < Nn;
    const float* xrow = x + (size_t)(rb + lrow) * 128 + lk;
    const float* wrow = W + (size_t)lrow * 128 + lk;
    u64 acc[8][4];
#pragma unroll
    for (int i = 0; i < 8; i++)
#pragma unroll
        for (int j = 0; j < 4; j++) acc[i][j] = 0ull;

    {
        float4 xv4 = rowok ? *(const float4*)xrow : make_float4(0.f, 0.f, 0.f, 0.f);
        float4 wv4 = *(const float4*)wrow;
        xs[0][lk + 0][lrow] = xv4.x; xs[0][lk + 1][lrow] = xv4.y;
        xs[0][lk + 2][lrow] = xv4.z; xs[0][lk + 3][lrow] = xv4.w;
        ws[0][lk + 0][lrow] = wv4.x; ws[0][lk + 1][lrow] = wv4.y;
        ws[0][lk + 2][lrow] = wv4.z; ws[0][lk + 3][lrow] = wv4.w;
    }
    __syncthreads();
    int p = 0;
    for (int kc = 8; kc <= 128; kc += 8) {
        float4 nx, nw;
        bool more = kc < 128;
        if (more) {
            nx = rowok ? *(const float4*)(xrow + kc) : make_float4(0.f, 0.f, 0.f, 0.f);
            nw = *(const float4*)(wrow + kc);
        }
#pragma unroll
        for (int kk = 0; kk < 8; kk++) {
            float4 xa = *(const float4*)&xs[p][kk][tr * 4];
            float4 xb = *(const float4*)&xs[p][kk][64 + tr * 4];
            ulonglong2 wlo = *(const ulonglong2*)&ws[p][kk][tc * 4];
            ulonglong2 whi = *(const ulonglong2*)&ws[p][kk][64 + tc * 4];
            float xr0[4] = {xa.x, xa.y, xa.z, xa.w};
            float xr1[4] = {xb.x, xb.y, xb.z, xb.w};
#pragma unroll
            for (int i = 0; i < 4; i++) {
                u64 xd = p2(xr0[i], xr0[i]);
                fma2(acc[i][0], xd, wlo.x);
                fma2(acc[i][1], xd, wlo.y);
                fma2(acc[i][2], xd, whi.x);
                fma2(acc[i][3], xd, whi.y);
            }
#pragma unroll
            for (int i = 0; i < 4; i++) {
                u64 xd = p2(xr1[i], xr1[i]);
                fma2(acc[4 + i][0], xd, wlo.x);
                fma2(acc[4 + i][1], xd, wlo.y);
                fma2(acc[4 + i][2], xd, whi.x);
                fma2(acc[4 + i][3], xd, whi.y);
            }
        }
        if (more) {
            int q = p ^ 1;
            xs[q][lk + 0][lrow] = nx.x; xs[q][lk + 1][lrow] = nx.y;
            xs[q][lk + 2][lrow] = nx.z; xs[q][lk + 3][lrow] = nx.w;
            ws[q][lk + 0][lrow] = nw.x; ws[q][lk + 1][lrow] = nw.y;
            ws[q][lk + 2][lrow] = nw.z; ws[q][lk + 3][lrow] = nw.w;
            __syncthreads();
            p = q;
        }
    }
#pragma unroll
    for (int i = 0; i < 8; i++) {
        int row = rb + (i < 4 ? tr * 4 + i : 64 + tr * 4 + (i - 4));
        if (row < Nn) {
            ulonglong2 v0; v0.x = acc[i][0]; v0.y = acc[i][1];
            ulonglong2 v1; v1.x = acc[i][2]; v1.y = acc[i][3];
            *(ulonglong2*)&g_P[(size_t)row * 256 + m * 128 + tc * 4]      = v0;
            *(ulonglong2*)&g_P[(size_t)row * 256 + m * 128 + 64 + tc * 4] = v1;
        }
    }
}

// ---------------- K4: fused logits + online-softmax aggregation --------------
__global__ void k_edge(const float* __restrict__ attn) {
    int wid = (blockIdx.x * blockDim.x + threadIdx.x) >> 5;
    int l = threadIdx.x & 31;
    if (wid >= Nn) return;
    int n = wid;
    const float4 dp = *(const float4*)&g_P[(size_t)n * 256 + 128 + 4 * l];
    float a0 = attn[4 * l], a1 = attn[4 * l + 1], a2 = attn[4 * l + 2], a3 = attn[4 * l + 3];
    float a0q = 0.2f * a0, a1q = 0.2f * a1, a2q = 0.2f * a2, a3q = 0.2f * a3;
    int beg = g_off[n], end = g_off[n + 1];
    float mh = -3.402823466e38f;
    float dh = 0.f;
    float4 acc = make_float4(0.f, 0.f, 0.f, 0.f);
    int i = beg;
    for (; i + 3 < end; i += 4) {
        int s0 = g_srcidx[i],     s1 = g_srcidx[i + 1];
        int s2 = g_srcidx[i + 2], s3 = g_srcidx[i + 3];
        float4 q0 = *(const float4*)&g_P[(size_t)s0 * 256 + 4 * l];
        float4 q1 = *(const float4*)&g_P[(size_t)s1 * 256 + 4 * l];
        float4 q2 = *(const float4*)&g_P[(size_t)s2 * 256 + 4 * l];
        float4 q3 = *(const float4*)&g_P[(size_t)s3 * 256 + 4 * l];
        float p0, p1, p2, p3;
        {
            float ex = q0.x + dp.x, ey = q0.y + dp.y, ez = q0.z + dp.z, ew = q0.w + dp.w;
            p0 = a0 * fmaxf(ex, 0.f) + a0q * fminf(ex, 0.f)
               + a1 * fmaxf(ey, 0.f) + a1q * fminf(ey, 0.f)
               + a2 * fmaxf(ez, 0.f) + a2q * fminf(ez, 0.f)
               + a3 * fmaxf(ew, 0.f) + a3q * fminf(ew, 0.f);
            ex = q1.x + dp.x; ey = q1.y + dp.y; ez = q1.z + dp.z; ew = q1.w + dp.w;
            p1 = a0 * fmaxf(ex, 0.f) + a0q * fminf(ex, 0.f)
               + a1 * fmaxf(ey, 0.f) + a1q * fminf(ey, 0.f)
               + a2 * fmaxf(ez, 0.f) + a2q * fminf(ez, 0.f)
               + a3 * fmaxf(ew, 0.f) + a3q * fminf(ew, 0.f);
            ex = q2.x + dp.x; ey = q2.y + dp.y; ez = q2.z + dp.z; ew = q2.w + dp.w;
            p2 = a0 * fmaxf(ex, 0.f) + a0q * fminf(ex, 0.f)
               + a1 * fmaxf(ey, 0.f) + a1q * fminf(ey, 0.f)
               + a2 * fmaxf(ez, 0.f) + a2q * fminf(ez, 0.f)
               + a3 * fmaxf(ew, 0.f) + a3q * fminf(ew, 0.f);
            ex = q3.x + dp.x; ey = q3.y + dp.y; ez = q3.z + dp.z; ew = q3.w + dp.w;
            p3 = a0 * fmaxf(ex, 0.f) + a0q * fminf(ex, 0.f)
               + a1 * fmaxf(ey, 0.f) + a1q * fminf(ey, 0.f)
               + a2 * fmaxf(ez, 0.f) + a2q * fminf(ez, 0.f)
               + a3 * fmaxf(ew, 0.f) + a3q * fminf(ew, 0.f);
        }
        p0 += __shfl_xor_sync(0xffffffffu, p0, 1);
        p1 += __shfl_xor_sync(0xffffffffu, p1, 1);
        p2 += __shfl_xor_sync(0xffffffffu, p2, 1);
        p3 += __shfl_xor_sync(0xffffffffu, p3, 1);
        p0 += __shfl_xor_sync(0xffffffffu, p0, 2);
        p1 += __shfl_xor_sync(0xffffffffu, p1, 2);
        p2 += __shfl_xor_sync(0xffffffffu, p2, 2);
        p3 += __shfl_xor_sync(0xffffffffu, p3, 2);
        float gm = fmaxf(fmaxf(p0, p1), fmaxf(p2, p3));
        float nm = fmaxf(mh, gm);
        float r  = __expf(mh - nm);
        float w0 = __expf(p0 - nm), w1 = __expf(p1 - nm);
        float w2 = __expf(p2 - nm), w3 = __expf(p3 - nm);
        dh = dh * r + (w0 + w1 + w2 + w3);
        acc.x = acc.x * r + w0 * q0.x + w1 * q1.x + w2 * q2.x + w3 * q3.x;
        acc.y = acc.y * r + w0 * q0.y + w1 * q1.y + w2 * q2.y + w3 * q3.y;
        acc.z = acc.z * r + w0 * q0.z + w1 * q1.z + w2 * q2.z + w3 * q3.z;
        acc.w = acc.w * r + w0 * q0.w + w1 * q1.w + w2 * q2.w + w3 * q3.w;
        mh = nm;
    }
    for (; i < end; i++) {
        int s0 = g_srcidx[i];
        float4 q0 = *(const float4*)&g_P[(size_t)s0 * 256 + 4 * l];
        float ex = q0.x + dp.x, ey = q0.y + dp.y, ez = q0.z + dp.z, ew = q0.w + dp.w;
        float p0 = a0 * fmaxf(ex, 0.f) + a0q * fminf(ex, 0.f)
                 + a1 * fmaxf(ey, 0.f) + a1q * fminf(ey, 0.f)
                 + a2 * fmaxf(ez, 0.f) + a2q * fminf(ez, 0.f)
                 + a3 * fmaxf(ew, 0.f) + a3q * fminf(ew, 0.f);
        p0 += __shfl_xor_sync(0xffffffffu, p0, 1);
        p0 += __shfl_xor_sync(0xffffffffu, p0, 2);
        float nm = fmaxf(mh, p0);
        float r  = __expf(mh - nm);
        float w0 = __expf(p0 - nm);
        dh = dh * r + w0;
        acc.x = acc.x * r + w0 * q0.x;
        acc.y = acc.y * r + w0 * q0.y;
        acc.z = acc.z * r + w0 * q0.z;
        acc.w = acc.w * r + w0 * q0.w;
        mh = nm;
    }
    *(float4*)&g_acc[(size_t)n * 128 + 4 * l] = acc;
    if ((l & 3) == 0) g_md[(size_t)n * 8 + (l >> 2)] = make_float2(mh, dh);
    if (beg < end) {
        float m = mh;
        for (int o = 16; o; o >>= 1) m = fmaxf(m, __shfl_xor_sync(0xffffffffu, m, o));
        if (l == 0) atomicMax(&g_maxenc, encf(m));
    }
}

// ---------------- K5: fused finalize + score GEMM (conflict-free split) ------
__global__ void k_score(const float* __restrict__ x, const float* __restrict__ bias,
                        const float* __restrict__ prelu, const float* __restrict__ Wsc,
                        float* out) {
    __shared__ __align__(16) float xs[2][8][128];
    __shared__ __align__(16) float ws[2][8][128];
    int t  = threadIdx.x;
    int tr = t >> 4, tc = t & 15;
    int rb = blockIdx.x * 128;
    int lrow = t & 127, lk = (t >> 7) * 4;
    bool rowok = (rb + lrow) < Nn;
    int row = rb + lrow;
    float al = prelu[0];
    float M = decf(g_maxenc);
    u64 acc[8][4];
#pragma unroll
    for (int i = 0; i < 8; i++)
#pragma unroll
        for (int j = 0; j < 4; j++) acc[i][j] = 0ull;

    auto loadout = [&](int k) -> float4 {
        float4 o4 = make_float4(0.f, 0.f, 0.f, 0.f);
        if (rowok) {
            float4 a4 = *(const float4*)&g_acc[(size_t)row * 128 + k];
            float2 md = g_md[(size_t)row * 8 + (k >> 4)];
            float s = __expf(md.x - M);
            float f = s / (s * md.y + 1e-16f);
            float4 x4 = *(const float4*)&x[(size_t)row * 128 + k];
            float4 b4 = *(const float4*)&bias[k];
            o4.x = a4.x * f + x4.x + b4.x; o4.x = o4.x > 0.f ? o4.x : al * o4.x;
            o4.y = a4.y * f + x4.y + b4.y; o4.y = o4.y > 0.f ? o4.y : al * o4.y;
            o4.z = a4.z * f + x4.z + b4.z; o4.z = o4.z > 0.f ? o4.z : al * o4.z;
            o4.w = a4.w * f + x4.w + b4.w; o4.w = o4.w > 0.f ? o4.w : al * o4.w;
            *(float4*)&out[(size_t)row * 128 + k] = o4;
        }
        return o4;
    };

    {
        float4 o4 = loadout(lk);
        float4 wv4 = *(const float4*)&Wsc[(size_t)lrow * 128 + lk];
        xs[0][lk + 0][lrow] = o4.x; xs[0][lk + 1][lrow] = o4.y;
        xs[0][lk + 2][lrow] = o4.z; xs[0][lk + 3][lrow] = o4.w;
        ws[0][lk + 0][lrow] = wv4.x; ws[0][lk + 1][lrow] = wv4.y;
        ws[0][lk + 2][lrow] = wv4.z; ws[0][lk + 3][lrow] = wv4.w;
    }
    __syncthreads();
    int p = 0;
    for (int kc = 8; kc <= 128; kc += 8) {
        float4 no4, nw4;
        bool more = kc < 128;
        if (more) {
            no4 = loadout(kc + lk);
            nw4 = *(const float4*)&Wsc[(size_t)lrow * 128 + kc + lk];
        }
#pragma unroll
        for (int kk = 0; kk < 8; kk++) {
            float4 xa = *(const float4*)&xs[p][kk][tr * 4];
            float4 xb = *(const float4*)&xs[p][kk][64 + tr * 4];
            ulonglong2 wlo = *(const ulonglong2*)&ws[p][kk][tc * 4];
            ulonglong2 whi = *(const ulonglong2*)&ws[p][kk][64 + tc * 4];
            float xr0[4] = {xa.x, xa.y, xa.z, xa.w};
            float xr1[4] = {xb.x, xb.y, xb.z, xb.w};
#pragma unroll
            for (int i = 0; i < 4; i++) {
                u64 xd = p2(xr0[i], xr0[i]);
                fma2(acc[i][0], xd, wlo.x);
                fma2(acc[i][1], xd, wlo.y);
                fma2(acc[i][2], xd, whi.x);
                fma2(acc[i][3], xd, whi.y);
            }
#pragma unroll
            for (int i = 0; i < 4; i++) {
                u64 xd = p2(xr1[i], xr1[i]);
                fma2(acc[4 + i][0], xd, wlo.x);
                fma2(acc[4 + i][1], xd, wlo.y);
                fma2(acc[4 + i][2], xd, whi.x);
                fma2(acc[4 + i][3], xd, whi.y);
            }
        }
        if (more) {
            int q = p ^ 1;
            xs[q][lk + 0][lrow] = no4.x; xs[q][lk + 1][lrow] = no4.y;
            xs[q][lk + 2][lrow] = no4.z; xs[q][lk + 3][lrow] = no4.w;
            ws[q][lk + 0][lrow] = nw4.x; ws[q][lk + 1][lrow] = nw4.y;
            ws[q][lk + 2][lrow] = nw4.z; ws[q][lk + 3][lrow] = nw4.w;
            __syncthreads();
            p = q;
        }
    }
#pragma unroll
    for (int i = 0; i < 8; i++) {
        int r2 = rb + (i < 4 ? tr * 4 + i : 64 + tr * 4 + (i - 4));
        if (r2 < Nn) {
            ulonglong2 v0; v0.x = acc[i][0]; v0.y = acc[i][1];
            ulonglong2 v1; v1.x = acc[i][2]; v1.y = acc[i][3];
            *(ulonglong2*)&g_score[(size_t)r2 * 128 + tc * 4]      = v0;
            *(ulonglong2*)&g_score[(size_t)r2 * 128 + 64 + tc * 4] = v1;
        }
    }
}

// ---------------- K6: light readout — block/graph, warp/node -----------------
__global__ void k_rd2(const float* __restrict__ out, const int* __restrict__ batch,
                      const float* __restrict__ ww, const float* __restrict__ bw,
                      const float* __restrict__ bsc, float* dout) {
    __shared__ __align__(16) float red[8 * 128];
    __shared__ int bnds[2];
    int t = threadIdx.x, g = blockIdx.x;
    int w = t >> 5, l = t & 31;
    if (t < 2) {
        int tgt = g + t;
        int lo = 0, hi = Nn;
        while (lo < hi) {
            int mid = (lo + hi) >> 1;
            if (batch[mid] < tgt) lo = mid + 1; else hi = mid;
        }
        bnds[t] = lo;
    }
    __syncthreads();
    int beg = bnds[0], end = bnds[1];
    const float4 aw  = *(const float4*)&ww[4 * l];
    const float4 bs4 = *(const float4*)&bsc[4 * l];
    float bw0 = bw[0];
    float4 sum = make_float4(0.f, 0.f, 0.f, 0.f);
    float4 mx  = make_float4(-3.402823466e38f, -3.402823466e38f,
                             -3.402823466e38f, -3.402823466e38f);
    for (int n = beg + w; n < end; n += 8) {
        float4 o4 = *(const float4*)&out[(size_t)n * 128 + 4 * l];
        float4 s4 = *(const float4*)&g_score[(size_t)n * 128 + 4 * l];
        float v = o4.x * aw.x + o4.y * aw.y + o4.z * aw.z + o4.w * aw.w;
#pragma unroll
        for (int o = 16; o; o >>= 1) v += __shfl_xor_sync(0xffffffffu, v, o);
        float gw = 1.f / (1.f + __expf(-(v + bw0)));
        sum.x += gw * (s4.x + bs4.x);
        sum.y += gw * (s4.y + bs4.y);
        sum.z += gw * (s4.z + bs4.z);
        sum.w += gw * (s4.w + bs4.w);
        mx.x = fmaxf(mx.x, o4.x); mx.y = fmaxf(mx.y, o4.y);
        mx.z = fmaxf(mx.z, o4.z); mx.w = fmaxf(mx.w, o4.w);
    }
    *(float4*)&red[w * 128 + 4 * l] = sum;
    __syncthreads();
    if (w == 0) {
        float4 tot = make_float4(0.f, 0.f, 0.f, 0.f);
#pragma unroll
        for (int r = 0; r < 8; r++) {
            float4 v = *(const float4*)&red[r * 128 + 4 * l];
            tot.x += v.x; tot.y += v.y; tot.z += v.z; tot.w += v.w;
        }
        *(float4*)&dout[(size_t)Nn * 128 + g * 256 + 4 * l] = tot;
    }
    __syncthreads();
    *(float4*)&red[w * 128 + 4 * l] = mx;
    __syncthreads();
    if (w == 0) {
        float4 tot = make_float4(-3.402823466e38f, -3.402823466e38f,
                                 -3.402823466e38f, -3.402823466e38f);
#pragma unroll
        for (int r = 0; r < 8; r++) {
            float4 v = *(const float4*)&red[r * 128 + 4 * l];
            tot.x = fmaxf(tot.x, v.x); tot.y = fmaxf(tot.y, v.y);
            tot.z = fmaxf(tot.z, v.z); tot.w = fmaxf(tot.w, v.w);
        }
        *(float4*)&dout[(size_t)Nn * 128 + g * 256 + 128 + 4 * l] = tot;
    }
}

// ---------------- launch: fork-join DAG ---------------------------------------
// main stream:  proj ──────────────┐
// side stream:  deg → scan → scatter ┴→ edge → score → rd2
extern "C" void kernel_launch(void* const* d_in, const int* in_sizes, int n_in,
                              void* d_out, int out_size) {
    const float* x     = (const float*)d_in[0];
    const int*   ei    = (const int*)d_in[1];
    const int*   batch = (const int*)d_in[2];
    const float* Wsrc  = (const float*)d_in[3];
    const float* Wdst  = (const float*)d_in[4];
    const float* attn  = (const float*)d_in[5];
    const float* bias  = (const float*)d_in[6];
    const float* prelu = (const float*)d_in[7];
    const float* ww    = (const float*)d_in[8];
    const float* bw    = (const float*)d_in[9];
    const float* Wsc   = (const float*)d_in[10];
    const float* bsc   = (const float*)d_in[11];
    float*       out   = (float*)d_out;

    // fork: side stream depends on the head of the main stream
    cudaEventRecord(g_ss.e0, 0);
    cudaStreamWaitEvent(g_ss.s, g_ss.e0, 0);

    // side chain: CSR build
    k_deg<<<(Ee + 511) / 512, 512, 0, g_ss.s>>>(ei);
    k_scan<<<NBLK, 256, 0, g_ss.s>>>();
    k_scatter<<<(Ee + 511) / 512, 512, 0, g_ss.s>>>(ei);
    cudaEventRecord(g_ss.e1, g_ss.s);

    // main: projection GEMM (independent of CSR build)
    dim3 gp(PROJ_BX, 2);
    k_proj<<<gp, 256>>>(x, Wsrc, Wdst);

    // join: edge phase needs both proj and CSR
    cudaStreamWaitEvent(0, g_ss.e1, 0);
    k_edge<<<Nn / 8, 256>>>(attn);
    k_score<<<PROJ_BX, 256>>>(x, bias, prelu, Wsc, out);
    k_rd2<<<Gg, 256>>>(out, batch, ww, bw, bsc, out);
}

// round 13
// speedup vs baseline: 3.2838x; 1.2642x over previous
#include <cuda_runtime.h>
#include <cstdint>

#define Nn 50000
#define Ee 800000
#define Gg 512
#define NBLK 196          // ceil(Nn/256)
#define PROJ_BX 391       // ceil(Nn/128)

// ---------------- scratch ----------------------------------------------------
__device__ __align__(16) float  g_P[(size_t)Nn * 256];    // [N][256]: 0..127 src_p, 128..255 dst_p
__device__ __align__(16) float  g_acc[(size_t)Nn * 128];  // unnormalized aggregation
__device__ __align__(16) float2 g_md[(size_t)Nn * 8];     // per (node,head): (max, denom)
__device__ __align__(16) float  g_u[(size_t)Gg * 128];    // per-graph gated sum of out
__device__ __align__(16) float  g_gws[Gg];                // per-graph sum of gates
__device__ __align__(16) int    g_deg[Nn];                // zero-init; self-cleaned
__device__ __align__(16) int    g_off[Nn + 1];
__device__ __align__(16) int    g_cur[Nn];
__device__ __align__(16) int    g_srcidx[Ee];
__device__ int      g_flag[NBLK];
__device__ int      g_done;
__device__ unsigned g_maxenc;

#define FLAG_A (1 << 24)
#define FLAG_P (1 << 25)
#define VALMSK 0xFFFFFF

// ---------------- streams/events (created at static init, pre-baseline) ------
struct SideStream {
    cudaStream_t s = nullptr, s2 = nullptr;
    cudaEvent_t  e0 = nullptr, e1 = nullptr, e2 = nullptr;
    SideStream() {
        cudaStreamCreateWithFlags(&s,  cudaStreamNonBlocking);
        cudaStreamCreateWithFlags(&s2, cudaStreamNonBlocking);
        cudaEventCreateWithFlags(&e0, cudaEventDisableTiming);
        cudaEventCreateWithFlags(&e1, cudaEventDisableTiming);
        cudaEventCreateWithFlags(&e2, cudaEventDisableTiming);
    }
};
static SideStream g_ss;

// ---------------- f32x2 packed helpers ---------------------------------------
typedef unsigned long long u64;
__device__ __forceinline__ u64 p2(float lo, float hi) {
    u64 r;
    asm("mov.b64 %0, {%1, %2};" : "=l"(r) : "r"(__float_as_uint(lo)), "r"(__float_as_uint(hi)));
    return r;
}
__device__ __forceinline__ void fma2(u64& d, u64 a, u64 b) {
    asm("fma.rn.f32x2 %0, %1, %2, %3;" : "=l"(d) : "l"(a), "l"(b), "l"(d));
}
__device__ __forceinline__ float2 up2(u64 v) {
    unsigned lo, hi;
    asm("mov.b64 {%0, %1}, %2;" : "=r"(lo), "=r"(hi) : "l"(v));
    return make_float2(__uint_as_float(lo), __uint_as_float(hi));
}
__device__ __forceinline__ unsigned encf(float f) {
    unsigned u = __float_as_uint(f);
    return (u & 0x80000000u) ? ~u : (u | 0x80000000u);
}
__device__ __forceinline__ float decf(unsigned e) {
    unsigned u = (e & 0x80000000u) ? (e & 0x7fffffffu) : ~e;
    return __uint_as_float(u);
}

// ---------------- K0: degree histogram ---------------------------------------
__global__ void k_deg(const int* __restrict__ ei) {
    int e = blockIdx.x * blockDim.x + threadIdx.x;
    if (e < Ee) atomicAdd(&g_deg[ei[Ee + e]], 1);
}

// ---------------- K1: decoupled-lookback exclusive scan ----------------------
__global__ void k_scan() {
    int b = blockIdx.x, t = threadIdx.x;
    int i = b * 256 + t;
    int v = (i < Nn) ? g_deg[i] : 0;
    if (i < Nn) g_deg[i] = 0;
    if (b == 0 && t == 1) g_maxenc = 0u;
    int lane = t & 31, w = t >> 5;
    int incl = v;
#pragma unroll
    for (int o = 1; o < 32; o <<= 1) {
        int u = __shfl_up_sync(0xffffffffu, incl, o);
        if (lane >= o) incl += u;
    }
    __shared__ int wsum[8];
    if (lane == 31) wsum[w] = incl;
    __syncthreads();
    if (w == 0) {
        int z = (lane < 8) ? wsum[lane] : 0;
#pragma unroll
        for (int o = 1; o < 8; o <<= 1) {
            int u = __shfl_up_sync(0xffffffffu, z, o);
            if (lane >= o) z += u;
        }
        if (lane < 8) wsum[lane] = z;
    }
    __syncthreads();
    incl += (w ? wsum[w - 1] : 0);
    __shared__ int blksum_s, prev_s;
    if (t == 255) blksum_s = incl;
    __syncthreads();
    int blksum = blksum_s;
    if (t == 0) {
        int prev = 0;
        if (b == 0) {
            atomicExch(&g_flag[0], FLAG_P | blksum);
        } else {
            atomicExch(&g_flag[b], FLAG_A | blksum);
            int j = b - 1;
            while (true) {
                int f;
                do { f = *(volatile int*)&g_flag[j]; } while (f == 0);
                prev += f & VALMSK;
                if (f & FLAG_P) break;
                j--;
            }
            atomicExch(&g_flag[b], FLAG_P | (prev + blksum));
        }
        prev_s = prev;
    }
    __syncthreads();
    int excl = prev_s + incl - v;
    if (i < Nn) { g_off[i] = excl; g_cur[i] = excl; }
    if (b == NBLK - 1 && t == 255) g_off[Nn] = prev_s + incl;
    if (t == 0) {
        int d = atomicAdd(&g_done, 1);
        if (d == NBLK - 1) {
            for (int j = 0; j < NBLK; j++) g_flag[j] = 0;
            g_done = 0;
        }
    }
}

// ---------------- K2: scatter edges into CSR slots ---------------------------
__global__ void k_scatter(const int* __restrict__ ei) {
    int e = blockIdx.x * blockDim.x + threadIdx.x;
    if (e < Ee) {
        int d = ei[Ee + e];
        int pos = atomicAdd(&g_cur[d], 1);
        g_srcidx[pos] = ei[e];
    }
}

// ---------------- K3: P = x @ W^T, 128x128 tile, conflict-free split tile ----
__global__ void k_proj(const float* __restrict__ x,
                       const float* __restrict__ Wsrc,
                       const float* __restrict__ Wdst) {
    __shared__ __align__(16) float xs[2][8][128];
    __shared__ __align__(16) float ws[2][8][128];
    int m = blockIdx.y;
    const float* W = m ? Wdst : Wsrc;
    int t  = threadIdx.x;
    int tr = t >> 4, tc = t & 15;
    int rb = blockIdx.x * 128;
    int lrow = t & 127, lk = (t >> 7) * 4;
    bool rowok = (rb + lrow) < Nn;
    const float* xrow = x + (size_t)(rb + lrow) * 128 + lk;
    const float* wrow = W + (size_t)lrow * 128 + lk;
    u64 acc[8][4];
#pragma unroll
    for (int i = 0; i < 8; i++)
#pragma unroll
        for (int j = 0; j < 4; j++) acc[i][j] = 0ull;

    {
        float4 xv4 = rowok ? *(const float4*)xrow : make_float4(0.f, 0.f, 0.f, 0.f);
        float4 wv4 = *(const float4*)wrow;
        xs[0][lk + 0][lrow] = xv4.x; xs[0][lk + 1][lrow] = xv4.y;
        xs[0][lk + 2][lrow] = xv4.z; xs[0][lk + 3][lrow] = xv4.w;
        ws[0][lk + 0][lrow] = wv4.x; ws[0][lk + 1][lrow] = wv4.y;
        ws[0][lk + 2][lrow] = wv4.z; ws[0][lk + 3][lrow] = wv4.w;
    }
    __syncthreads();
    int p = 0;
    for (int kc = 8; kc <= 128; kc += 8) {
        float4 nx, nw;
        bool more = kc < 128;
        if (more) {
            nx = rowok ? *(const float4*)(xrow + kc) : make_float4(0.f, 0.f, 0.f, 0.f);
            nw = *(const float4*)(wrow + kc);
        }
#pragma unroll
        for (int kk = 0; kk < 8; kk++) {
            float4 xa = *(const float4*)&xs[p][kk][tr * 4];
            float4 xb = *(const float4*)&xs[p][kk][64 + tr * 4];
            ulonglong2 wlo = *(const ulonglong2*)&ws[p][kk][tc * 4];
            ulonglong2 whi = *(const ulonglong2*)&ws[p][kk][64 + tc * 4];
            float xr0[4] = {xa.x, xa.y, xa.z, xa.w};
            float xr1[4] = {xb.x, xb.y, xb.z, xb.w};
#pragma unroll
            for (int i = 0; i < 4; i++) {
                u64 xd = p2(xr0[i], xr0[i]);
                fma2(acc[i][0], xd, wlo.x);
                fma2(acc[i][1], xd, wlo.y);
                fma2(acc[i][2], xd, whi.x);
                fma2(acc[i][3], xd, whi.y);
            }
#pragma unroll
            for (int i = 0; i < 4; i++) {
                u64 xd = p2(xr1[i], xr1[i]);
                fma2(acc[4 + i][0], xd, wlo.x);
                fma2(acc[4 + i][1], xd, wlo.y);
                fma2(acc[4 + i][2], xd, whi.x);
                fma2(acc[4 + i][3], xd, whi.y);
            }
        }
        if (more) {
            int q = p ^ 1;
            xs[q][lk + 0][lrow] = nx.x; xs[q][lk + 1][lrow] = nx.y;
            xs[q][lk + 2][lrow] = nx.z; xs[q][lk + 3][lrow] = nx.w;
            ws[q][lk + 0][lrow] = nw.x; ws[q][lk + 1][lrow] = nw.y;
            ws[q][lk + 2][lrow] = nw.z; ws[q][lk + 3][lrow] = nw.w;
            __syncthreads();
            p = q;
        }
    }
#pragma unroll
    for (int i = 0; i < 8; i++) {
        int row = rb + (i < 4 ? tr * 4 + i : 64 + tr * 4 + (i - 4));
        if (row < Nn) {
            ulonglong2 v0; v0.x = acc[i][0]; v0.y = acc[i][1];
            ulonglong2 v1; v1.x = acc[i][2]; v1.y = acc[i][3];
            *(ulonglong2*)&g_P[(size_t)row * 256 + m * 128 + tc * 4]      = v0;
            *(ulonglong2*)&g_P[(size_t)row * 256 + m * 128 + 64 + tc * 4] = v1;
        }
    }
}

// ---------------- K4: fused logits + online-softmax aggregation --------------
__global__ void k_edge(const float* __restrict__ attn) {
    int wid = (blockIdx.x * blockDim.x + threadIdx.x) >> 5;
    int l = threadIdx.x & 31;
    if (wid >= Nn) return;
    int n = wid;
    const float4 dp = *(const float4*)&g_P[(size_t)n * 256 + 128 + 4 * l];
    float a0 = attn[4 * l], a1 = attn[4 * l + 1], a2 = attn[4 * l + 2], a3 = attn[4 * l + 3];
    float a0q = 0.2f * a0, a1q = 0.2f * a1, a2q = 0.2f * a2, a3q = 0.2f * a3;
    int beg = g_off[n], end = g_off[n + 1];
    float mh = -3.402823466e38f;
    float dh = 0.f;
    float4 acc = make_float4(0.f, 0.f, 0.f, 0.f);
    int i = beg;
    for (; i + 3 < end; i += 4) {
        int s0 = g_srcidx[i],     s1 = g_srcidx[i + 1];
        int s2 = g_srcidx[i + 2], s3 = g_srcidx[i + 3];
        float4 q0 = *(const float4*)&g_P[(size_t)s0 * 256 + 4 * l];
        float4 q1 = *(const float4*)&g_P[(size_t)s1 * 256 + 4 * l];
        float4 q2 = *(const float4*)&g_P[(size_t)s2 * 256 + 4 * l];
        float4 q3 = *(const float4*)&g_P[(size_t)s3 * 256 + 4 * l];
        float p0, p1, p2, p3;
        {
            float ex = q0.x + dp.x, ey = q0.y + dp.y, ez = q0.z + dp.z, ew = q0.w + dp.w;
            p0 = a0 * fmaxf(ex, 0.f) + a0q * fminf(ex, 0.f)
               + a1 * fmaxf(ey, 0.f) + a1q * fminf(ey, 0.f)
               + a2 * fmaxf(ez, 0.f) + a2q * fminf(ez, 0.f)
               + a3 * fmaxf(ew, 0.f) + a3q * fminf(ew, 0.f);
            ex = q1.x + dp.x; ey = q1.y + dp.y; ez = q1.z + dp.z; ew = q1.w + dp.w;
            p1 = a0 * fmaxf(ex, 0.f) + a0q * fminf(ex, 0.f)
               + a1 * fmaxf(ey, 0.f) + a1q * fminf(ey, 0.f)
               + a2 * fmaxf(ez, 0.f) + a2q * fminf(ez, 0.f)
               + a3 * fmaxf(ew, 0.f) + a3q * fminf(ew, 0.f);
            ex = q2.x + dp.x; ey = q2.y + dp.y; ez = q2.z + dp.z; ew = q2.w + dp.w;
            p2 = a0 * fmaxf(ex, 0.f) + a0q * fminf(ex, 0.f)
               + a1 * fmaxf(ey, 0.f) + a1q * fminf(ey, 0.f)
               + a2 * fmaxf(ez, 0.f) + a2q * fminf(ez, 0.f)
               + a3 * fmaxf(ew, 0.f) + a3q * fminf(ew, 0.f);
            ex = q3.x + dp.x; ey = q3.y + dp.y; ez = q3.z + dp.z; ew = q3.w + dp.w;
            p3 = a0 * fmaxf(ex, 0.f) + a0q * fminf(ex, 0.f)
               + a1 * fmaxf(ey, 0.f) + a1q * fminf(ey, 0.f)
               + a2 * fmaxf(ez, 0.f) + a2q * fminf(ez, 0.f)
               + a3 * fmaxf(ew, 0.f) + a3q * fminf(ew, 0.f);
        }
        p0 += __shfl_xor_sync(0xffffffffu, p0, 1);
        p1 += __shfl_xor_sync(0xffffffffu, p1, 1);
        p2 += __shfl_xor_sync(0xffffffffu, p2, 1);
        p3 += __shfl_xor_sync(0xffffffffu, p3, 1);
        p0 += __shfl_xor_sync(0xffffffffu, p0, 2);
        p1 += __shfl_xor_sync(0xffffffffu, p1, 2);
        p2 += __shfl_xor_sync(0xffffffffu, p2, 2);
        p3 += __shfl_xor_sync(0xffffffffu, p3, 2);
        float gm = fmaxf(fmaxf(p0, p1), fmaxf(p2, p3));
        float nm = fmaxf(mh, gm);
        float r  = __expf(mh - nm);
        float w0 = __expf(p0 - nm), w1 = __expf(p1 - nm);
        float w2 = __expf(p2 - nm), w3 = __expf(p3 - nm);
        dh = dh * r + (w0 + w1 + w2 + w3);
        acc.x = acc.x * r + w0 * q0.x + w1 * q1.x + w2 * q2.x + w3 * q3.x;
        acc.y = acc.y * r + w0 * q0.y + w1 * q1.y + w2 * q2.y + w3 * q3.y;
        acc.z = acc.z * r + w0 * q0.z + w1 * q1.z + w2 * q2.z + w3 * q3.z;
        acc.w = acc.w * r + w0 * q0.w + w1 * q1.w + w2 * q2.w + w3 * q3.w;
        mh = nm;
    }
    for (; i < end; i++) {
        int s0 = g_srcidx[i];
        float4 q0 = *(const float4*)&g_P[(size_t)s0 * 256 + 4 * l];
        float ex = q0.x + dp.x, ey = q0.y + dp.y, ez = q0.z + dp.z, ew = q0.w + dp.w;
        float p0 = a0 * fmaxf(ex, 0.f) + a0q * fminf(ex, 0.f)
                 + a1 * fmaxf(ey, 0.f) + a1q * fminf(ey, 0.f)
                 + a2 * fmaxf(ez, 0.f) + a2q * fminf(ez, 0.f)
                 + a3 * fmaxf(ew, 0.f) + a3q * fminf(ew, 0.f);
        p0 += __shfl_xor_sync(0xffffffffu, p0, 1);
        p0 += __shfl_xor_sync(0xffffffffu, p0, 2);
        float nm = fmaxf(mh, p0);
        float r  = __expf(mh - nm);
        float w0 = __expf(p0 - nm);
        dh = dh * r + w0;
        acc.x = acc.x * r + w0 * q0.x;
        acc.y = acc.y * r + w0 * q0.y;
        acc.z = acc.z * r + w0 * q0.z;
        acc.w = acc.w * r + w0 * q0.w;
        mh = nm;
    }
    *(float4*)&g_acc[(size_t)n * 128 + 4 * l] = acc;
    if ((l & 3) == 0) g_md[(size_t)n * 8 + (l >> 2)] = make_float2(mh, dh);
    if (beg < end) {
        float m = mh;
        for (int o = 16; o; o >>= 1) m = fmaxf(m, __shfl_xor_sync(0xffffffffu, m, o));
        if (l == 0) atomicMax(&g_maxenc, encf(m));
    }
}

// ---------------- K5: finalize — normalize + residual + PReLU ----------------
__global__ void k_fin(const float* __restrict__ x, const float* __restrict__ bias,
                      const float* __restrict__ prelu, float* out) {
    int wid = (blockIdx.x * blockDim.x + threadIdx.x) >> 5;
    int l = threadIdx.x & 31;
    if (wid >= Nn) return;
    int n = wid;
    float M = decf(g_maxenc);
    float2 md = g_md[(size_t)n * 8 + (l >> 2)];
    float s = __expf(md.x - M);             // empty node: exp(-inf)=0 -> f=0
    float f = s / (s * md.y + 1e-16f);
    float4 a4 = *(const float4*)&g_acc[(size_t)n * 128 + 4 * l];
    const float4 xv = *(const float4*)&x[(size_t)n * 128 + 4 * l];
    const float4 bv = *(const float4*)&bias[4 * l];
    float al = prelu[0];
    float o0 = a4.x * f + xv.x + bv.x; o0 = o0 > 0.f ? o0 : al * o0;
    float o1 = a4.y * f + xv.y + bv.y; o1 = o1 > 0.f ? o1 : al * o1;
    float o2 = a4.z * f + xv.z + bv.z; o2 = o2 > 0.f ? o2 : al * o2;
    float o3 = a4.w * f + xv.w + bv.w; o3 = o3 > 0.f ? o3 : al * o3;
    *(float4*)&out[(size_t)n * 128 + 4 * l] = make_float4(o0, o1, o2, o3);
}

// ---------------- K6: readout scan — gates, u_g, gws, max-pool ---------------
__global__ void k_rd3(const float* __restrict__ out, const int* __restrict__ batch,
                      const float* __restrict__ ww, const float* __restrict__ bw,
                      float* dout) {
    __shared__ __align__(16) float redu[8 * 128];
    __shared__ __align__(16) float redm[8 * 128];
    __shared__ float gwss[8];
    __shared__ int bnds[2];
    int t = threadIdx.x, g = blockIdx.x;
    int w = t >> 5, l = t & 31;
    if (t < 2) {
        int tgt = g + t;
        int lo = 0, hi = Nn;
        while (lo < hi) {
            int mid = (lo + hi) >> 1;
            if (batch[mid] < tgt) lo = mid + 1; else hi = mid;
        }
        bnds[t] = lo;
    }
    __syncthreads();
    int beg = bnds[0], end = bnds[1];
    const float4 aw = *(const float4*)&ww[4 * l];
    float bw0 = bw[0];
    float4 us = make_float4(0.f, 0.f, 0.f, 0.f);
    float4 mx = make_float4(-3.402823466e38f, -3.402823466e38f,
                            -3.402823466e38f, -3.402823466e38f);
    float gws = 0.f;
    for (int n = beg + w; n < end; n += 8) {
        float4 o4 = *(const float4*)&out[(size_t)n * 128 + 4 * l];
        float v = o4.x * aw.x + o4.y * aw.y + o4.z * aw.z + o4.w * aw.w;
#pragma unroll
        for (int o = 16; o; o >>= 1) v += __shfl_xor_sync(0xffffffffu, v, o);
        float gw = 1.f / (1.f + __expf(-(v + bw0)));
        us.x += gw * o4.x; us.y += gw * o4.y;
        us.z += gw * o4.z; us.w += gw * o4.w;
        mx.x = fmaxf(mx.x, o4.x); mx.y = fmaxf(mx.y, o4.y);
        mx.z = fmaxf(mx.z, o4.z); mx.w = fmaxf(mx.w, o4.w);
        gws += gw;
    }
    *(float4*)&redu[w * 128 + 4 * l] = us;
    *(float4*)&redm[w * 128 + 4 * l] = mx;
    if (l == 0) gwss[w] = gws;
    __syncthreads();
    if (w == 0) {
        float4 tu = make_float4(0.f, 0.f, 0.f, 0.f);
        float4 tm = make_float4(-3.402823466e38f, -3.402823466e38f,
                                -3.402823466e38f, -3.402823466e38f);
#pragma unroll
        for (int r = 0; r < 8; r++) {
            float4 vu = *(const float4*)&redu[r * 128 + 4 * l];
            float4 vm = *(const float4*)&redm[r * 128 + 4 * l];
            tu.x += vu.x; tu.y += vu.y; tu.z += vu.z; tu.w += vu.w;
            tm.x = fmaxf(tm.x, vm.x); tm.y = fmaxf(tm.y, vm.y);
            tm.z = fmaxf(tm.z, vm.z); tm.w = fmaxf(tm.w, vm.w);
        }
        *(float4*)&g_u[(size_t)g * 128 + 4 * l] = tu;
        *(float4*)&dout[(size_t)Nn * 128 + g * 256 + 128 + 4 * l] = tm;
        if (l == 0) {
            float s = 0.f;
#pragma unroll
            for (int r = 0; r < 8; r++) s += gwss[r];
            g_gws[g] = s;
        }
    }
}

// ---------------- K7: micro-GEMM g_sum = u @ Wsc^T + gws*bsc -----------------
// M=512 graphs, N=128, K=128. 4 blocks, proj skeleton.
__global__ void k_gsum(const float* __restrict__ Wsc, const float* __restrict__ bsc,
                       float* dout) {
    __shared__ __align__(16) float xs[2][8][128];
    __shared__ __align__(16) float ws[2][8][128];
    int t  = threadIdx.x;
    int tr = t >> 4, tc = t & 15;
    int rb = blockIdx.x * 128;
    int lrow = t & 127, lk = (t >> 7) * 4;
    const float* urow = g_u + (size_t)(rb + lrow) * 128 + lk;
    const float* wrow = Wsc + (size_t)lrow * 128 + lk;
    u64 acc[8][4];
#pragma unroll
    for (int i = 0; i < 8; i++)
#pragma unroll
        for (int j = 0; j < 4; j++) acc[i][j] = 0ull;

    {
        float4 xv4 = *(const float4*)urow;
        float4 wv4 = *(const float4*)wrow;
        xs[0][lk + 0][lrow] = xv4.x; xs[0][lk + 1][lrow] = xv4.y;
        xs[0][lk + 2][lrow] = xv4.z; xs[0][lk + 3][lrow] = xv4.w;
        ws[0][lk + 0][lrow] = wv4.x; ws[0][lk + 1][lrow] = wv4.y;
        ws[0][lk + 2][lrow] = wv4.z; ws[0][lk + 3][lrow] = wv4.w;
    }
    __syncthreads();
    int p = 0;
    for (int kc = 8; kc <= 128; kc += 8) {
        float4 nx, nw;
        bool more = kc < 128;
        if (more) {
            nx = *(const float4*)(urow + kc);
            nw = *(const float4*)(wrow + kc);
        }
#pragma unroll
        for (int kk = 0; kk < 8; kk++) {
            float4 xa = *(const float4*)&xs[p][kk][tr * 4];
            float4 xb = *(const float4*)&xs[p][kk][64 + tr * 4];
            ulonglong2 wlo = *(const ulonglong2*)&ws[p][kk][tc * 4];
            ulonglong2 whi = *(const ulonglong2*)&ws[p][kk][64 + tc * 4];
            float xr0[4] = {xa.x, xa.y, xa.z, xa.w};
            float xr1[4] = {xb.x, xb.y, xb.z, xb.w};
#pragma unroll
            for (int i = 0; i < 4; i++) {
                u64 xd = p2(xr0[i], xr0[i]);
                fma2(acc[i][0], xd, wlo.x);
                fma2(acc[i][1], xd, wlo.y);
                fma2(acc[i][2], xd, whi.x);
                fma2(acc[i][3], xd, whi.y);
            }
#pragma unroll
            for (int i = 0; i < 4; i++) {
                u64 xd = p2(xr1[i], xr1[i]);
                fma2(acc[4 + i][0], xd, wlo.x);
                fma2(acc[4 + i][1], xd, wlo.y);
                fma2(acc[4 + i][2], xd, whi.x);
                fma2(acc[4 + i][3], xd, whi.y);
            }
        }
        if (more) {
            int q = p ^ 1;
            xs[q][lk + 0][lrow] = nx.x; xs[q][lk + 1][lrow] = nx.y;
            xs[q][lk + 2][lrow] = nx.z; xs[q][lk + 3][lrow] = nx.w;
            ws[q][lk + 0][lrow] = nw.x; ws[q][lk + 1][lrow] = nw.y;
            ws[q][lk + 2][lrow] = nw.z; ws[q][lk + 3][lrow] = nw.w;
            __syncthreads();
            p = q;
        }
    }
#pragma unroll
    for (int i = 0; i < 8; i++) {
        int row = rb + (i < 4 ? tr * 4 + i : 64 + tr * 4 + (i - 4));   // graph id
        float gws = g_gws[row];
        float2 c0 = up2(acc[i][0]);
        float2 c1 = up2(acc[i][1]);
        float2 c2 = up2(acc[i][2]);
        float2 c3 = up2(acc[i][3]);
        int j0 = tc * 4, j1 = 64 + tc * 4;
        float4 b0 = *(const float4*)&bsc[j0];
        float4 b1 = *(const float4*)&bsc[j1];
        float4 o0 = make_float4(c0.x + gws * b0.x, c0.y + gws * b0.y,
                                c1.x + gws * b0.z, c1.y + gws * b0.w);
        float4 o1 = make_float4(c2.x + gws * b1.x, c2.y + gws * b1.y,
                                c3.x + gws * b1.z, c3.y + gws * b1.w);
        *(float4*)&dout[(size_t)Nn * 128 + (size_t)row * 256 + j0] = o0;
        *(float4*)&dout[(size_t)Nn * 128 + (size_t)row * 256 + j1] = o1;
    }
}

// ---------------- launch: fork-join DAG ---------------------------------------
// s2: proj ────────────────────────┐
// s : deg → scan → scatter ────────┴→ [0]: edge → fin → rd3 → gsum
extern "C" void kernel_launch(void* const* d_in, const int* in_sizes, int n_in,
                              void* d_out, int out_size) {
    const float* x     = (const float*)d_in[0];
    const int*   ei    = (const int*)d_in[1];
    const int*   batch = (const int*)d_in[2];
    const float* Wsrc  = (const float*)d_in[3];
    const float* Wdst  = (const float*)d_in[4];
    const float* attn  = (const float*)d_in[5];
    const float* bias  = (const float*)d_in[6];
    const float* prelu = (const float*)d_in[7];
    const float* ww    = (const float*)d_in[8];
    const float* bw    = (const float*)d_in[9];
    const float* Wsc   = (const float*)d_in[10];
    const float* bsc   = (const float*)d_in[11];
    float*       out   = (float*)d_out;

    cudaEventRecord(g_ss.e0, 0);
    cudaStreamWaitEvent(g_ss.s,  g_ss.e0, 0);
    cudaStreamWaitEvent(g_ss.s2, g_ss.e0, 0);

    dim3 gp(PROJ_BX, 2);
    k_proj<<<gp, 256, 0, g_ss.s2>>>(x, Wsrc, Wdst);                // 0
    k_deg<<<(Ee + 511) / 512, 512, 0, g_ss.s>>>(ei);               // 1
    k_scan<<<NBLK, 256, 0, g_ss.s>>>();                            // 2
    k_scatter<<<(Ee + 511) / 512, 512, 0, g_ss.s>>>(ei);           // 3 <- ncu slot
    cudaEventRecord(g_ss.e1, g_ss.s);
    cudaEventRecord(g_ss.e2, g_ss.s2);
    cudaStreamWaitEvent(0, g_ss.e1, 0);
    cudaStreamWaitEvent(0, g_ss.e2, 0);

    k_edge<<<Nn / 8, 256>>>(attn);                                 // 4
    k_fin<<<Nn / 8, 256>>>(x, bias, prelu, out);                   // 5
    k_rd3<<<Gg, 256>>>(out, batch, ww, bw, out);                   // 6
    k_gsum<<<4, 256>>>(Wsc, bsc, out);                             // 7
}